// round 11
// baseline (speedup 1.0000x reference)
#include <cuda_runtime.h>
#include <cuda_fp16.h>
#include <math.h>

#define Nn 50000
#define Ee 1600000
#define DIN 128
#define DH 64
#define BN_EPS 1e-5f

// ---------------- scratch (device globals; no allocation allowed) -------------
__device__ float  g_w[Ee];            // mixed weight (pre-norm)
__device__ int2   g_idx[Ee];          // (src, dst) as int32
__device__ int2   g_csr[Ee];          // dst-sorted: (src, bitcast(norm))
__device__ float2 g_degcnt[Nn];       // (weighted degree incl self, count) via red.v2
__device__ float  g_dinv[Nn];         // rsqrt(deg)
__device__ int    g_part[50176];      // block-local exclusive scan
__device__ int    g_bsum[196];
__device__ int    g_row_off[Nn + 1];  // CSR row offsets
__device__ int    g_cursor[Nn];       // fill cursors
__device__ __half g_h1h[Nn * DH];     // x @ W1            (fp16 payload)
__device__ __half g_h2h[Nn * DH];     // relu(bn1)@W2      (fp16 payload)
__device__ float  g_agg1[Nn * DH];
__device__ float  g_agg2[Nn * DH];
__device__ float  g_sum1[DH], g_sq1[DH], g_sum2[DH], g_sq2[DH];
__device__ float  g_a;

// ---------------- init: deg=(1,0) self-loop, BN stats, sigmoid(alpha) --------
__global__ void init_kernel(const float* __restrict__ alpha) {
    int i = blockIdx.x * blockDim.x + threadIdx.x;
    if (i < Nn) g_degcnt[i] = make_float2(1.0f, 0.0f);
    if (i < DH) { g_sum1[i] = 0.f; g_sq1[i] = 0.f; g_sum2[i] = 0.f; g_sq2[i] = 0.f; }
    if (i == 0) g_a = 1.0f / (1.0f + expf(-alpha[0]));
}

// ---------------- mix weights, record (src,dst), fused degree+count red ------
// Standalone (0 smem) so the atomic/latency-bound work runs at full occupancy.
// Per-block dtype detection: OR of 256 sampled high-words (L2-hot, ~free).
__global__ void mix_deg_kernel(const void* __restrict__ ei,
                               const float* __restrict__ wsc,
                               const float* __restrict__ wfc) {
    int tid = threadIdx.x;
    int any = __syncthreads_or((int)((const unsigned*)ei)[2 * tid + 1]);
    int is64 = (any == 0);
    int e = blockIdx.x * blockDim.x + tid;
    if (e >= Ee) return;
    int s, d;
    if (is64) {
        const long long* p = (const long long*)ei;   // full-8B loads: full sectors
        s = (int)p[e];
        d = (int)p[(size_t)Ee + e];
    } else {
        const int* p = (const int*)ei;
        s = p[e];
        d = p[Ee + e];
    }
    float a = g_a;
    float w = a * wsc[e] + (1.0f - a) * wfc[e];
    g_w[e] = w;
    g_idx[e] = make_int2(s, d);
    float* dp = (float*)&g_degcnt[d];
    asm volatile("red.global.add.v2.f32 [%0], {%1,%2};"
                 :: "l"(dp), "f"(w), "f"(1.0f) : "memory");
}

// ---------------- GEMM1: h1 = x @ W1 (fp16 store) ----------------------------
__global__ void gemm1_kernel(const float* __restrict__ x,
                             const float* __restrict__ W1) {
    __shared__ float sW[DIN * DH];      // 32 KB
    __shared__ float sx[32][DIN];       // 16 KB
    int tid = threadIdx.x;
    for (int i = tid; i < DIN * DH; i += 256) sW[i] = W1[i];
    __syncthreads();
    int warp = tid >> 5, lane = tid & 31;

    for (int base = blockIdx.x * 32; base < Nn; base += gridDim.x * 32) {
        int r0 = base + warp * 4;
        #pragma unroll
        for (int r = 0; r < 4; r++) {
            int row = r0 + r;
            if (row < Nn) {
                #pragma unroll
                for (int j = 0; j < 4; j++)
                    sx[warp * 4 + r][lane + j * 32] = x[(size_t)row * DIN + lane + j * 32];
            }
        }
        __syncwarp();

        float acc[4][2] = {};
        #pragma unroll 8
        for (int k4 = 0; k4 < DIN / 4; k4++) {
            float4 xv[4];
            #pragma unroll
            for (int r = 0; r < 4; r++)
                xv[r] = *reinterpret_cast<const float4*>(&sx[warp * 4 + r][k4 * 4]);
            #pragma unroll
            for (int kk = 0; kk < 4; kk++) {
                int k = k4 * 4 + kk;
                float w0 = sW[k * DH + lane];
                float w1v = sW[k * DH + lane + 32];
                #pragma unroll
                for (int r = 0; r < 4; r++) {
                    float xs = (kk == 0) ? xv[r].x : (kk == 1) ? xv[r].y : (kk == 2) ? xv[r].z : xv[r].w;
                    acc[r][0] = fmaf(xs, w0, acc[r][0]);
                    acc[r][1] = fmaf(xs, w1v, acc[r][1]);
                }
            }
        }

        #pragma unroll
        for (int r = 0; r < 4; r++) {
            int row = r0 + r;
            if (row < Nn) {
                g_h1h[row * DH + lane] = __float2half_rn(acc[r][0]);
                g_h1h[row * DH + lane + 32] = __float2half_rn(acc[r][1]);
            }
        }
        __syncwarp();
    }
}

// ---------------- scan part A (+ dinv fused) ---------------------------------
__global__ void scan_a_kernel() {
    __shared__ int s[256];
    int i = blockIdx.x * 256 + threadIdx.x;
    int v = 0;
    if (i < Nn) {
        float2 dc = g_degcnt[i];
        v = (int)dc.y;
        g_dinv[i] = (dc.x > 0.f) ? rsqrtf(fmaxf(dc.x, 1e-12f)) : 0.f;
    }
    s[threadIdx.x] = v;
    __syncthreads();
    #pragma unroll
    for (int off = 1; off < 256; off <<= 1) {
        int t = (threadIdx.x >= off) ? s[threadIdx.x - off] : 0;
        __syncthreads();
        s[threadIdx.x] += t;
        __syncthreads();
    }
    g_part[i] = s[threadIdx.x] - v;
    if (threadIdx.x == 255) g_bsum[blockIdx.x] = s[255];
}

// ---------------- scan B+C merged: each block redundantly scans g_bsum -------
__global__ void scan_bc_kernel() {
    __shared__ int s[256];
    __shared__ int s_off;
    int tid = threadIdx.x;
    int v = (tid < 196) ? g_bsum[tid] : 0;
    s[tid] = v;
    __syncthreads();
    #pragma unroll
    for (int off = 1; off < 256; off <<= 1) {
        int t = (tid >= off) ? s[tid - off] : 0;
        __syncthreads();
        s[tid] += t;
        __syncthreads();
    }
    if (tid == blockIdx.x) s_off = s[tid] - v;   // exclusive prefix of this block
    __syncthreads();
    int i = blockIdx.x * 256 + tid;
    if (i < Nn) {
        int o = g_part[i] + s_off;
        g_row_off[i] = o;
        g_cursor[i] = o;
    }
    if (i == 0) g_row_off[Nn] = Ee;
}

// ---------------- CSR fill: norm computed here -------------------------------
__global__ void fill_kernel() {
    int e = blockIdx.x * blockDim.x + threadIdx.x;
    if (e >= Ee) return;
    int2 sd = g_idx[e];
    float nrm = g_w[e] * g_dinv[sd.x] * g_dinv[sd.y];
    int pos = atomicAdd(&g_cursor[sd.y], 1);
    g_csr[pos] = make_int2(sd.x, __float_as_int(nrm));
}

// ---------------- CSR aggregation (fp16 gather, fp32 acc) + BN stats ---------
// One warp per dst row; half-warps (16 lanes x 4 halves = full 64-col row).
// Per edge each lane loads 8B (uint2 = 4 fp16), converts, fp32-FMAs.
#define GATH(E, A) {                                                            \
    uint2 _u = *reinterpret_cast<const uint2*>(h + (size_t)(E).x * DH + l4);    \
    float _w = __int_as_float((E).y);                                           \
    float2 _fa = __half22float2(*reinterpret_cast<__half2*>(&_u.x));            \
    float2 _fb = __half22float2(*reinterpret_cast<__half2*>(&_u.y));            \
    A.x = fmaf(_fa.x, _w, A.x); A.y = fmaf(_fa.y, _w, A.y);                     \
    A.z = fmaf(_fb.x, _w, A.z); A.w = fmaf(_fb.y, _w, A.w); }

template <int L>
__global__ void agg_kernel(const float* __restrict__ bias) {
    const __half* __restrict__ h = (L == 1) ? g_h1h : g_h2h;
    float* agg  = (L == 1) ? g_agg1 : g_agg2;
    float* gsum = (L == 1) ? g_sum1 : g_sum2;
    float* gsq  = (L == 1) ? g_sq1  : g_sq2;

    __shared__ int2 stage[8][32];

    int tid = threadIdx.x;
    int w = tid >> 5, lane = tid & 31, half = lane >> 4;
    int l4 = (lane & 15) * 4;
    int wg = (blockIdx.x << 3) + w;
    int nw = gridDim.x << 3;
    float4 bb = *reinterpret_cast<const float4*>(bias + l4);
    float ls0 = 0, ls1 = 0, ls2 = 0, ls3 = 0;
    float lq0 = 0, lq1 = 0, lq2 = 0, lq3 = 0;

    for (int r = wg; r < Nn; r += nw) {
        int beg = g_row_off[r], end = g_row_off[r + 1];
        float4 a0, a1, a2, a3;
        a1 = a2 = a3 = make_float4(0.f, 0.f, 0.f, 0.f);
        if (half == 0) {
            float di = g_dinv[r];
            float sn = di * di;  // self-loop: dinv*1*dinv
            uint2 u = *reinterpret_cast<const uint2*>(h + (size_t)r * DH + l4);
            float2 fa = __half22float2(*reinterpret_cast<__half2*>(&u.x));
            float2 fb = __half22float2(*reinterpret_cast<__half2*>(&u.y));
            a0 = make_float4(fmaf(fa.x, sn, bb.x), fmaf(fa.y, sn, bb.y),
                             fmaf(fb.x, sn, bb.z), fmaf(fb.y, sn, bb.w));
        } else {
            a0 = make_float4(0.f, 0.f, 0.f, 0.f);
        }

        for (int base = beg; base < end; base += 32) {
            int m = end - base;
            if (m > 32) m = 32;
            // stage (coalesced); pad with weight-0 entries (src 0 valid, FMA no-op)
            stage[w][lane] = (lane < m) ? g_csr[base + lane] : make_int2(0, 0);
            __syncwarp();

            int jj = 0;
            for (; jj + 8 <= m; jj += 8) {
                int2 e0 = stage[w][jj + half];
                int2 e1 = stage[w][jj + 2 + half];
                int2 e2 = stage[w][jj + 4 + half];
                int2 e3 = stage[w][jj + 6 + half];
                GATH(e0, a0); GATH(e1, a1); GATH(e2, a2); GATH(e3, a3);
            }
            if (jj < m) {
                int2 e0 = stage[w][jj + half];
                int2 e1 = stage[w][jj + 2 + half];
                int2 e2 = stage[w][jj + 4 + half];
                int2 e3 = stage[w][jj + 6 + half];
                GATH(e0, a0); GATH(e1, a1); GATH(e2, a2); GATH(e3, a3);
            }
            __syncwarp();
        }

        float4 acc = make_float4(a0.x + a1.x + a2.x + a3.x,
                                 a0.y + a1.y + a2.y + a3.y,
                                 a0.z + a1.z + a2.z + a3.z,
                                 a0.w + a1.w + a2.w + a3.w);
        acc.x += __shfl_xor_sync(0xffffffffu, acc.x, 16);
        acc.y += __shfl_xor_sync(0xffffffffu, acc.y, 16);
        acc.z += __shfl_xor_sync(0xffffffffu, acc.z, 16);
        acc.w += __shfl_xor_sync(0xffffffffu, acc.w, 16);
        if (half == 0) {
            *reinterpret_cast<float4*>(agg + (size_t)r * DH + l4) = acc;
            ls0 += acc.x; lq0 = fmaf(acc.x, acc.x, lq0);
            ls1 += acc.y; lq1 = fmaf(acc.y, acc.y, lq1);
            ls2 += acc.z; lq2 = fmaf(acc.z, acc.z, lq2);
            ls3 += acc.w; lq3 = fmaf(acc.w, acc.w, lq3);
        }
    }

    // block reduction of BN stats, then 128 atomics per block
    __shared__ float ssum[8][64], ssq[8][64];
    if (half == 0) {
        ssum[w][l4 + 0] = ls0; ssum[w][l4 + 1] = ls1;
        ssum[w][l4 + 2] = ls2; ssum[w][l4 + 3] = ls3;
        ssq[w][l4 + 0] = lq0;  ssq[w][l4 + 1] = lq1;
        ssq[w][l4 + 2] = lq2;  ssq[w][l4 + 3] = lq3;
    }
    __syncthreads();
    if (tid < 64) {
        float S = 0.f, Q = 0.f;
        #pragma unroll
        for (int ww = 0; ww < 8; ww++) { S += ssum[ww][tid]; Q += ssq[ww][tid]; }
        atomicAdd(&gsum[tid], S);
        atomicAdd(&gsq[tid], Q);
    }
}

// ---------------- GEMM2: h2 = relu(bn1(agg1)) @ W2 (fp16 store) --------------
__global__ void gemm2_kernel(const float* __restrict__ W2,
                             const float* __restrict__ gamma1,
                             const float* __restrict__ beta1) {
    __shared__ float sW[DH * DH];   // 16 KB
    __shared__ float sx[32][DH];    // 8 KB
    __shared__ float s_scale[DH], s_shift[DH];
    int tid = threadIdx.x;
    if (tid < DH) {
        float mean = g_sum1[tid] * (1.0f / Nn);
        float var = g_sq1[tid] * (1.0f / Nn) - mean * mean;
        float sc = gamma1[tid] * rsqrtf(var + BN_EPS);
        s_scale[tid] = sc;
        s_shift[tid] = fmaf(-mean, sc, beta1[tid]);
    }
    for (int i = tid; i < DH * DH; i += 256) sW[i] = W2[i];
    __syncthreads();
    int warp = tid >> 5, lane = tid & 31;

    for (int base = blockIdx.x * 32; base < Nn; base += gridDim.x * 32) {
        int r0 = base + warp * 4;
        #pragma unroll
        for (int r = 0; r < 4; r++) {
            int row = r0 + r;
            if (row < Nn) {
                #pragma unroll
                for (int j = 0; j < 2; j++) {
                    int c = lane + j * 32;
                    float v = g_agg1[(size_t)row * DH + c];
                    sx[warp * 4 + r][c] = fmaxf(fmaf(v, s_scale[c], s_shift[c]), 0.f);
                }
            }
        }
        __syncwarp();

        float acc[4][2] = {};
        #pragma unroll 4
        for (int k4 = 0; k4 < DH / 4; k4++) {
            float4 xv[4];
            #pragma unroll
            for (int r = 0; r < 4; r++)
                xv[r] = *reinterpret_cast<const float4*>(&sx[warp * 4 + r][k4 * 4]);
            #pragma unroll
            for (int kk = 0; kk < 4; kk++) {
                int k = k4 * 4 + kk;
                float w0 = sW[k * DH + lane];
                float w1v = sW[k * DH + lane + 32];
                #pragma unroll
                for (int r = 0; r < 4; r++) {
                    float xs = (kk == 0) ? xv[r].x : (kk == 1) ? xv[r].y : (kk == 2) ? xv[r].z : xv[r].w;
                    acc[r][0] = fmaf(xs, w0, acc[r][0]);
                    acc[r][1] = fmaf(xs, w1v, acc[r][1]);
                }
            }
        }

        #pragma unroll
        for (int r = 0; r < 4; r++) {
            int row = r0 + r;
            if (row < Nn) {
                g_h2h[row * DH + lane] = __float2half_rn(acc[r][0]);
                g_h2h[row * DH + lane + 32] = __float2half_rn(acc[r][1]);
            }
        }
        __syncwarp();
    }
}

// ---------------- final: out = relu(bn2(agg2)) -------------------------------
__global__ void final_kernel(const float* __restrict__ gamma2,
                             const float* __restrict__ beta2,
                             float* __restrict__ out) {
    __shared__ float s_scale[DH], s_shift[DH];
    int tid = threadIdx.x;
    if (tid < DH) {
        float mean = g_sum2[tid] * (1.0f / Nn);
        float var = g_sq2[tid] * (1.0f / Nn) - mean * mean;
        float sc = gamma2[tid] * rsqrtf(var + BN_EPS);
        s_scale[tid] = sc;
        s_shift[tid] = fmaf(-mean, sc, beta2[tid]);
    }
    __syncthreads();
    int i = blockIdx.x * 256 + tid;
    if (i < Nn * DH) {
        int c = i & 63;
        out[i] = fmaxf(fmaf(g_agg2[i], s_scale[c], s_shift[c]), 0.f);
    }
}

// -----------------------------------------------------------------------------
extern "C" void kernel_launch(void* const* d_in, const int* in_sizes, int n_in,
                              void* d_out, int out_size) {
    const float* x      = (const float*)d_in[0];
    const void*  ei_sc  = d_in[1];
    const float* w_sc   = (const float*)d_in[2];
    // d_in[3] = edge_index_fc (unused by reference)
    const float* w_fc   = (const float*)d_in[4];
    const float* alpha  = (const float*)d_in[5];
    const float* W1     = (const float*)d_in[6];
    const float* b1     = (const float*)d_in[7];
    const float* W2     = (const float*)d_in[8];
    const float* b2     = (const float*)d_in[9];
    const float* gamma1 = (const float*)d_in[10];
    const float* beta1  = (const float*)d_in[11];
    const float* gamma2 = (const float*)d_in[12];
    const float* beta2  = (const float*)d_in[13];
    float* out = (float*)d_out;

    const int TB = 256;
    const int nblkE = (Ee + TB - 1) / TB;       // 6250

    init_kernel<<<196, TB>>>(alpha);
    mix_deg_kernel<<<nblkE, TB>>>(ei_sc, w_sc, w_fc);
    gemm1_kernel<<<592, TB>>>(x, W1);
    scan_a_kernel<<<196, TB>>>();
    scan_bc_kernel<<<196, TB>>>();
    fill_kernel<<<nblkE, TB>>>();
    agg_kernel<1><<<592, TB>>>(b1);
    gemm2_kernel<<<592, TB>>>(W2, gamma1, beta1);
    agg_kernel<2><<<592, TB>>>(b2);
    final_kernel<<<(Nn * DH + TB - 1) / TB, TB>>>(gamma2, beta2, out);
}

// round 12
// speedup vs baseline: 1.1910x; 1.1910x over previous
#include <cuda_runtime.h>
#include <math.h>

#define Nn 50000
#define Ee 1600000
#define DIN 128
#define DH 64
#define BN_EPS 1e-5f

// ---------------- scratch (device globals; no allocation allowed) -------------
__device__ float  g_w[Ee];            // mixed weight (pre-norm)
__device__ int2   g_idx[Ee];          // (src, dst) as int32
__device__ int2   g_csr[Ee];          // dst-sorted: (src, bitcast(norm))
__device__ float2 g_degcnt[Nn];       // (weighted degree incl self, count) via red.v2
__device__ float  g_dinv[Nn];         // rsqrt(deg)
__device__ int    g_part[50176];      // block-local exclusive scan
__device__ int    g_bsum[196];
__device__ int    g_row_off[Nn + 1];  // CSR row offsets
__device__ int    g_cursor[Nn];       // fill cursors
__device__ float  g_h1[Nn * DH];      // x @ W1           (fp32: agg is issue-bound,
__device__ float  g_h2[Nn * DH];      //  fp16 payload measured SLOWER in R10/R11)
__device__ float  g_agg1[Nn * DH];
__device__ float  g_agg2[Nn * DH];
__device__ float  g_sum1[DH], g_sq1[DH], g_sum2[DH], g_sq2[DH];
__device__ float  g_a;

// ---------------- init: deg=(1,0) self-loop, BN stats, sigmoid(alpha) --------
__global__ void init_kernel(const float* __restrict__ alpha) {
    int i = blockIdx.x * blockDim.x + threadIdx.x;
    if (i < Nn) g_degcnt[i] = make_float2(1.0f, 0.0f);
    if (i < DH) { g_sum1[i] = 0.f; g_sq1[i] = 0.f; g_sum2[i] = 0.f; g_sq2[i] = 0.f; }
    if (i == 0) g_a = 1.0f / (1.0f + expf(-alpha[0]));
}

// ---------------- mix weights, record (src,dst), fused degree+count red ------
// 0 smem -> full occupancy. Per-block dtype detect: OR of 256 sampled high
// words (L2-hot after block 0, effectively free).
__global__ void mix_deg_kernel(const void* __restrict__ ei,
                               const float* __restrict__ wsc,
                               const float* __restrict__ wfc) {
    int tid = threadIdx.x;
    int any = __syncthreads_or((int)((const unsigned*)ei)[2 * tid + 1]);
    int is64 = (any == 0);
    int e = blockIdx.x * blockDim.x + tid;
    if (e >= Ee) return;
    int s, d;
    if (is64) {
        const long long* p = (const long long*)ei;   // full-8B loads: full sectors
        s = (int)p[e];
        d = (int)p[(size_t)Ee + e];
    } else {
        const int* p = (const int*)ei;
        s = p[e];
        d = p[Ee + e];
    }
    float a = g_a;
    float w = a * wsc[e] + (1.0f - a) * wfc[e];
    g_w[e] = w;
    g_idx[e] = make_int2(s, d);
    float* dp = (float*)&g_degcnt[d];
    asm volatile("red.global.add.v2.f32 [%0], {%1,%2};"
                 :: "l"(dp), "f"(w), "f"(1.0f) : "memory");
}

// ---------------- scan part A (+ dinv fused) ---------------------------------
__global__ void scan_a_kernel() {
    __shared__ int s[256];
    int i = blockIdx.x * 256 + threadIdx.x;
    int v = 0;
    if (i < Nn) {
        float2 dc = g_degcnt[i];
        v = (int)dc.y;
        g_dinv[i] = (dc.x > 0.f) ? rsqrtf(fmaxf(dc.x, 1e-12f)) : 0.f;
    }
    s[threadIdx.x] = v;
    __syncthreads();
    #pragma unroll
    for (int off = 1; off < 256; off <<= 1) {
        int t = (threadIdx.x >= off) ? s[threadIdx.x - off] : 0;
        __syncthreads();
        s[threadIdx.x] += t;
        __syncthreads();
    }
    g_part[i] = s[threadIdx.x] - v;
    if (threadIdx.x == 255) g_bsum[blockIdx.x] = s[255];
}

// ---------------- GEMM1: h1 = x @ W1 (launch slot 3 -> gets ncu profile) -----
__global__ void gemm1_kernel(const float* __restrict__ x,
                             const float* __restrict__ W1) {
    __shared__ float sW[DIN * DH];      // 32 KB
    __shared__ float sx[32][DIN];       // 16 KB
    int tid = threadIdx.x;
    for (int i = tid; i < DIN * DH; i += 256) sW[i] = W1[i];
    __syncthreads();
    int warp = tid >> 5, lane = tid & 31;

    for (int base = blockIdx.x * 32; base < Nn; base += gridDim.x * 32) {
        int r0 = base + warp * 4;
        #pragma unroll
        for (int r = 0; r < 4; r++) {
            int row = r0 + r;
            if (row < Nn) {
                #pragma unroll
                for (int j = 0; j < 4; j++)
                    sx[warp * 4 + r][lane + j * 32] = x[(size_t)row * DIN + lane + j * 32];
            }
        }
        __syncwarp();

        float acc[4][2] = {};
        #pragma unroll 8
        for (int k4 = 0; k4 < DIN / 4; k4++) {
            float4 xv[4];
            #pragma unroll
            for (int r = 0; r < 4; r++)
                xv[r] = *reinterpret_cast<const float4*>(&sx[warp * 4 + r][k4 * 4]);
            #pragma unroll
            for (int kk = 0; kk < 4; kk++) {
                int k = k4 * 4 + kk;
                float w0 = sW[k * DH + lane];
                float w1v = sW[k * DH + lane + 32];
                #pragma unroll
                for (int r = 0; r < 4; r++) {
                    float xs = (kk == 0) ? xv[r].x : (kk == 1) ? xv[r].y : (kk == 2) ? xv[r].z : xv[r].w;
                    acc[r][0] = fmaf(xs, w0, acc[r][0]);
                    acc[r][1] = fmaf(xs, w1v, acc[r][1]);
                }
            }
        }

        #pragma unroll
        for (int r = 0; r < 4; r++) {
            int row = r0 + r;
            if (row < Nn) {
                g_h1[row * DH + lane] = acc[r][0];
                g_h1[row * DH + lane + 32] = acc[r][1];
            }
        }
        __syncwarp();
    }
}

// ---------------- scan B+C merged: each block redundantly scans g_bsum -------
__global__ void scan_bc_kernel() {
    __shared__ int s[256];
    __shared__ int s_off;
    int tid = threadIdx.x;
    int v = (tid < 196) ? g_bsum[tid] : 0;
    s[tid] = v;
    __syncthreads();
    #pragma unroll
    for (int off = 1; off < 256; off <<= 1) {
        int t = (tid >= off) ? s[tid - off] : 0;
        __syncthreads();
        s[tid] += t;
        __syncthreads();
    }
    if (tid == blockIdx.x) s_off = s[tid] - v;   // exclusive prefix of this block
    __syncthreads();
    int i = blockIdx.x * 256 + tid;
    if (i < Nn) {
        int o = g_part[i] + s_off;
        g_row_off[i] = o;
        g_cursor[i] = o;
    }
    if (i == 0) g_row_off[Nn] = Ee;
}

// ---------------- CSR fill: norm computed here -------------------------------
__global__ void fill_kernel() {
    int e = blockIdx.x * blockDim.x + threadIdx.x;
    if (e >= Ee) return;
    int2 sd = g_idx[e];
    float nrm = g_w[e] * g_dinv[sd.x] * g_dinv[sd.y];
    int pos = atomicAdd(&g_cursor[sd.y], 1);
    g_csr[pos] = make_int2(sd.x, __float_as_int(nrm));
}

// ---------------- CSR aggregation (fp32 gather) + fused BN stats -------------
// One warp per dst row; half-warps (16 lanes x float4 = full 64-col row)
// process interleaved edges with 4 independent accumulator chains. Edge
// metadata staged in smem (coalesced LDG+STS per 32 edges, broadcast LDS).
template <int L>
__global__ void agg_kernel(const float* __restrict__ bias) {
    const float* __restrict__ h = (L == 1) ? g_h1 : g_h2;
    float* agg  = (L == 1) ? g_agg1 : g_agg2;
    float* gsum = (L == 1) ? g_sum1 : g_sum2;
    float* gsq  = (L == 1) ? g_sq1  : g_sq2;

    __shared__ int2 stage[8][32];

    int tid = threadIdx.x;
    int w = tid >> 5, lane = tid & 31, half = lane >> 4;
    int l4 = (lane & 15) * 4;
    int wg = (blockIdx.x << 3) + w;
    int nw = gridDim.x << 3;
    float4 bb = *reinterpret_cast<const float4*>(bias + l4);
    float ls0 = 0, ls1 = 0, ls2 = 0, ls3 = 0;
    float lq0 = 0, lq1 = 0, lq2 = 0, lq3 = 0;

    for (int r = wg; r < Nn; r += nw) {
        int beg = g_row_off[r], end = g_row_off[r + 1];
        float4 a0, a1, a2, a3;
        a1 = a2 = a3 = make_float4(0.f, 0.f, 0.f, 0.f);
        if (half == 0) {
            float di = g_dinv[r];
            float sn = di * di;  // self-loop: dinv*1*dinv
            float4 hv = *reinterpret_cast<const float4*>(h + (size_t)r * DH + l4);
            a0 = make_float4(fmaf(hv.x, sn, bb.x), fmaf(hv.y, sn, bb.y),
                             fmaf(hv.z, sn, bb.z), fmaf(hv.w, sn, bb.w));
        } else {
            a0 = make_float4(0.f, 0.f, 0.f, 0.f);
        }

        for (int base = beg; base < end; base += 32) {
            int m = end - base;
            if (m > 32) m = 32;
            // stage (coalesced); pad with weight-0 entries (src 0 valid, FMA no-op)
            stage[w][lane] = (lane < m) ? g_csr[base + lane] : make_int2(0, 0);
            __syncwarp();

            int jj = 0;
            for (; jj + 8 <= m; jj += 8) {
                int2 e0 = stage[w][jj + half];
                int2 e1 = stage[w][jj + 2 + half];
                int2 e2 = stage[w][jj + 4 + half];
                int2 e3 = stage[w][jj + 6 + half];
                float4 v0 = *reinterpret_cast<const float4*>(h + (size_t)e0.x * DH + l4);
                float4 v1 = *reinterpret_cast<const float4*>(h + (size_t)e1.x * DH + l4);
                float4 v2 = *reinterpret_cast<const float4*>(h + (size_t)e2.x * DH + l4);
                float4 v3 = *reinterpret_cast<const float4*>(h + (size_t)e3.x * DH + l4);
                float w0 = __int_as_float(e0.y), w1 = __int_as_float(e1.y);
                float w2 = __int_as_float(e2.y), w3 = __int_as_float(e3.y);
                a0.x = fmaf(v0.x, w0, a0.x); a0.y = fmaf(v0.y, w0, a0.y);
                a0.z = fmaf(v0.z, w0, a0.z); a0.w = fmaf(v0.w, w0, a0.w);
                a1.x = fmaf(v1.x, w1, a1.x); a1.y = fmaf(v1.y, w1, a1.y);
                a1.z = fmaf(v1.z, w1, a1.z); a1.w = fmaf(v1.w, w1, a1.w);
                a2.x = fmaf(v2.x, w2, a2.x); a2.y = fmaf(v2.y, w2, a2.y);
                a2.z = fmaf(v2.z, w2, a2.z); a2.w = fmaf(v2.w, w2, a2.w);
                a3.x = fmaf(v3.x, w3, a3.x); a3.y = fmaf(v3.y, w3, a3.y);
                a3.z = fmaf(v3.z, w3, a3.z); a3.w = fmaf(v3.w, w3, a3.w);
            }
            if (jj < m) {
                int2 e0 = stage[w][jj + half];
                int2 e1 = stage[w][jj + 2 + half];
                int2 e2 = stage[w][jj + 4 + half];
                int2 e3 = stage[w][jj + 6 + half];
                float4 v0 = *reinterpret_cast<const float4*>(h + (size_t)e0.x * DH + l4);
                float4 v1 = *reinterpret_cast<const float4*>(h + (size_t)e1.x * DH + l4);
                float4 v2 = *reinterpret_cast<const float4*>(h + (size_t)e2.x * DH + l4);
                float4 v3 = *reinterpret_cast<const float4*>(h + (size_t)e3.x * DH + l4);
                float w0 = __int_as_float(e0.y), w1 = __int_as_float(e1.y);
                float w2 = __int_as_float(e2.y), w3 = __int_as_float(e3.y);
                a0.x = fmaf(v0.x, w0, a0.x); a0.y = fmaf(v0.y, w0, a0.y);
                a0.z = fmaf(v0.z, w0, a0.z); a0.w = fmaf(v0.w, w0, a0.w);
                a1.x = fmaf(v1.x, w1, a1.x); a1.y = fmaf(v1.y, w1, a1.y);
                a1.z = fmaf(v1.z, w1, a1.z); a1.w = fmaf(v1.w, w1, a1.w);
                a2.x = fmaf(v2.x, w2, a2.x); a2.y = fmaf(v2.y, w2, a2.y);
                a2.z = fmaf(v2.z, w2, a2.z); a2.w = fmaf(v2.w, w2, a2.w);
                a3.x = fmaf(v3.x, w3, a3.x); a3.y = fmaf(v3.y, w3, a3.y);
                a3.z = fmaf(v3.z, w3, a3.z); a3.w = fmaf(v3.w, w3, a3.w);
            }
            __syncwarp();
        }

        float4 acc = make_float4(a0.x + a1.x + a2.x + a3.x,
                                 a0.y + a1.y + a2.y + a3.y,
                                 a0.z + a1.z + a2.z + a3.z,
                                 a0.w + a1.w + a2.w + a3.w);
        acc.x += __shfl_xor_sync(0xffffffffu, acc.x, 16);
        acc.y += __shfl_xor_sync(0xffffffffu, acc.y, 16);
        acc.z += __shfl_xor_sync(0xffffffffu, acc.z, 16);
        acc.w += __shfl_xor_sync(0xffffffffu, acc.w, 16);
        if (half == 0) {
            *reinterpret_cast<float4*>(agg + (size_t)r * DH + l4) = acc;
            ls0 += acc.x; lq0 = fmaf(acc.x, acc.x, lq0);
            ls1 += acc.y; lq1 = fmaf(acc.y, acc.y, lq1);
            ls2 += acc.z; lq2 = fmaf(acc.z, acc.z, lq2);
            ls3 += acc.w; lq3 = fmaf(acc.w, acc.w, lq3);
        }
    }

    // block reduction of BN stats, then 128 atomics per block
    __shared__ float ssum[8][64], ssq[8][64];
    if (half == 0) {
        ssum[w][l4 + 0] = ls0; ssum[w][l4 + 1] = ls1;
        ssum[w][l4 + 2] = ls2; ssum[w][l4 + 3] = ls3;
        ssq[w][l4 + 0] = lq0;  ssq[w][l4 + 1] = lq1;
        ssq[w][l4 + 2] = lq2;  ssq[w][l4 + 3] = lq3;
    }
    __syncthreads();
    if (tid < 64) {
        float S = 0.f, Q = 0.f;
        #pragma unroll
        for (int ww = 0; ww < 8; ww++) { S += ssum[ww][tid]; Q += ssq[ww][tid]; }
        atomicAdd(&gsum[tid], S);
        atomicAdd(&gsq[tid], Q);
    }
}

// ---------------- GEMM2: h2 = relu(bn1(agg1)) @ W2 ---------------------------
__global__ void gemm2_kernel(const float* __restrict__ W2,
                             const float* __restrict__ gamma1,
                             const float* __restrict__ beta1) {
    __shared__ float sW[DH * DH];   // 16 KB
    __shared__ float sx[32][DH];    // 8 KB
    __shared__ float s_scale[DH], s_shift[DH];
    int tid = threadIdx.x;
    if (tid < DH) {
        float mean = g_sum1[tid] * (1.0f / Nn);
        float var = g_sq1[tid] * (1.0f / Nn) - mean * mean;
        float sc = gamma1[tid] * rsqrtf(var + BN_EPS);
        s_scale[tid] = sc;
        s_shift[tid] = fmaf(-mean, sc, beta1[tid]);
    }
    for (int i = tid; i < DH * DH; i += 256) sW[i] = W2[i];
    __syncthreads();
    int warp = tid >> 5, lane = tid & 31;

    for (int base = blockIdx.x * 32; base < Nn; base += gridDim.x * 32) {
        int r0 = base + warp * 4;
        #pragma unroll
        for (int r = 0; r < 4; r++) {
            int row = r0 + r;
            if (row < Nn) {
                #pragma unroll
                for (int j = 0; j < 2; j++) {
                    int c = lane + j * 32;
                    float v = g_agg1[(size_t)row * DH + c];
                    sx[warp * 4 + r][c] = fmaxf(fmaf(v, s_scale[c], s_shift[c]), 0.f);
                }
            }
        }
        __syncwarp();

        float acc[4][2] = {};
        #pragma unroll 4
        for (int k4 = 0; k4 < DH / 4; k4++) {
            float4 xv[4];
            #pragma unroll
            for (int r = 0; r < 4; r++)
                xv[r] = *reinterpret_cast<const float4*>(&sx[warp * 4 + r][k4 * 4]);
            #pragma unroll
            for (int kk = 0; kk < 4; kk++) {
                int k = k4 * 4 + kk;
                float w0 = sW[k * DH + lane];
                float w1v = sW[k * DH + lane + 32];
                #pragma unroll
                for (int r = 0; r < 4; r++) {
                    float xs = (kk == 0) ? xv[r].x : (kk == 1) ? xv[r].y : (kk == 2) ? xv[r].z : xv[r].w;
                    acc[r][0] = fmaf(xs, w0, acc[r][0]);
                    acc[r][1] = fmaf(xs, w1v, acc[r][1]);
                }
            }
        }

        #pragma unroll
        for (int r = 0; r < 4; r++) {
            int row = r0 + r;
            if (row < Nn) {
                g_h2[row * DH + lane] = acc[r][0];
                g_h2[row * DH + lane + 32] = acc[r][1];
            }
        }
        __syncwarp();
    }
}

// ---------------- final: out = relu(bn2(agg2)) -------------------------------
__global__ void final_kernel(const float* __restrict__ gamma2,
                             const float* __restrict__ beta2,
                             float* __restrict__ out) {
    __shared__ float s_scale[DH], s_shift[DH];
    int tid = threadIdx.x;
    if (tid < DH) {
        float mean = g_sum2[tid] * (1.0f / Nn);
        float var = g_sq2[tid] * (1.0f / Nn) - mean * mean;
        float sc = gamma2[tid] * rsqrtf(var + BN_EPS);
        s_scale[tid] = sc;
        s_shift[tid] = fmaf(-mean, sc, beta2[tid]);
    }
    __syncthreads();
    int i = blockIdx.x * 256 + tid;
    if (i < Nn * DH) {
        int c = i & 63;
        out[i] = fmaxf(fmaf(g_agg2[i], s_scale[c], s_shift[c]), 0.f);
    }
}

// -----------------------------------------------------------------------------
extern "C" void kernel_launch(void* const* d_in, const int* in_sizes, int n_in,
                              void* d_out, int out_size) {
    const float* x      = (const float*)d_in[0];
    const void*  ei_sc  = d_in[1];
    const float* w_sc   = (const float*)d_in[2];
    // d_in[3] = edge_index_fc (unused by reference)
    const float* w_fc   = (const float*)d_in[4];
    const float* alpha  = (const float*)d_in[5];
    const float* W1     = (const float*)d_in[6];
    const float* b1     = (const float*)d_in[7];
    const float* W2     = (const float*)d_in[8];
    const float* b2     = (const float*)d_in[9];
    const float* gamma1 = (const float*)d_in[10];
    const float* beta1  = (const float*)d_in[11];
    const float* gamma2 = (const float*)d_in[12];
    const float* beta2  = (const float*)d_in[13];
    float* out = (float*)d_out;

    const int TB = 256;
    const int nblkE = (Ee + TB - 1) / TB;       // 6250

    // gemm1 deliberately placed as 4th launch (idx 3): the harness ncu capture
    // consistently profiles launch index 3, giving attribution on a hot kernel.
    init_kernel<<<196, TB>>>(alpha);                          // idx 0
    mix_deg_kernel<<<nblkE, TB>>>(ei_sc, w_sc, w_fc);         // idx 1
    scan_a_kernel<<<196, TB>>>();                             // idx 2
    gemm1_kernel<<<592, TB>>>(x, W1);                         // idx 3  <- profiled
    scan_bc_kernel<<<196, TB>>>();                            // idx 4
    fill_kernel<<<nblkE, TB>>>();                             // idx 5
    agg_kernel<1><<<592, TB>>>(b1);                           // idx 6
    gemm2_kernel<<<592, TB>>>(W2, gamma1, beta1);             // idx 7
    agg_kernel<2><<<592, TB>>>(b2);                           // idx 8
    final_kernel<<<(Nn * DH + TB - 1) / TB, TB>>>(gamma2, beta2, out);  // idx 9
}

// round 13
// speedup vs baseline: 1.1956x; 1.0039x over previous
#include <cuda_runtime.h>
#include <math.h>

#define Nn 50000
#define Ee 1600000
#define DIN 128
#define DH 64
#define BN_EPS 1e-5f

// ---------------- scratch (device globals; no allocation allowed) -------------
__device__ float  g_w[Ee];            // mixed weight (pre-norm)
__device__ int2   g_idx[Ee];          // (src, dst) as int32
__device__ int2   g_csr[Ee];          // dst-sorted: (src, bitcast(norm))
__device__ float2 g_degcnt[Nn];       // (weighted degree incl self, count) via red.v2
__device__ float  g_dinv[Nn];         // rsqrt(deg)
__device__ int    g_part[50176];      // block-local exclusive scan
__device__ int    g_bsum[196];
__device__ int    g_row_off[Nn + 1];  // CSR row offsets
__device__ int    g_cursor[Nn];       // fill cursors
__device__ float  g_h1[Nn * DH];      // x @ W1  (fp32: agg is issue-bound; fp16 was slower)
__device__ float  g_h2[Nn * DH];
__device__ float  g_agg1[Nn * DH];
__device__ float  g_agg2[Nn * DH];
__device__ float  g_sum1[DH], g_sq1[DH], g_sum2[DH], g_sq2[DH];
__device__ float  g_a;

// ---------------- init: deg=(1,0) self-loop, BN stats, sigmoid(alpha) --------
__global__ void init_kernel(const float* __restrict__ alpha) {
    int i = blockIdx.x * blockDim.x + threadIdx.x;
    if (i < Nn) g_degcnt[i] = make_float2(1.0f, 0.0f);
    if (i < DH) { g_sum1[i] = 0.f; g_sq1[i] = 0.f; g_sum2[i] = 0.f; g_sq2[i] = 0.f; }
    if (i == 0) g_a = 1.0f / (1.0f + expf(-alpha[0]));
}

// ---------------- mix weights, record (src,dst), fused degree+count red ------
__global__ void mix_deg_kernel(const void* __restrict__ ei,
                               const float* __restrict__ wsc,
                               const float* __restrict__ wfc) {
    int tid = threadIdx.x;
    int any = __syncthreads_or((int)((const unsigned*)ei)[2 * tid + 1]);
    int is64 = (any == 0);
    int e = blockIdx.x * blockDim.x + tid;
    if (e >= Ee) return;
    int s, d;
    if (is64) {
        const long long* p = (const long long*)ei;   // full-8B loads: full sectors
        s = (int)p[e];
        d = (int)p[(size_t)Ee + e];
    } else {
        const int* p = (const int*)ei;
        s = p[e];
        d = p[Ee + e];
    }
    float a = g_a;
    float w = a * wsc[e] + (1.0f - a) * wfc[e];
    g_w[e] = w;
    g_idx[e] = make_int2(s, d);
    float* dp = (float*)&g_degcnt[d];
    asm volatile("red.global.add.v2.f32 [%0], {%1,%2};"
                 :: "l"(dp), "f"(w), "f"(1.0f) : "memory");
}

// ---------------- scan part A (+ dinv fused) ---------------------------------
__global__ void scan_a_kernel() {
    __shared__ int s[256];
    int i = blockIdx.x * 256 + threadIdx.x;
    int v = 0;
    if (i < Nn) {
        float2 dc = g_degcnt[i];
        v = (int)dc.y;
        g_dinv[i] = (dc.x > 0.f) ? rsqrtf(fmaxf(dc.x, 1e-12f)) : 0.f;
    }
    s[threadIdx.x] = v;
    __syncthreads();
    #pragma unroll
    for (int off = 1; off < 256; off <<= 1) {
        int t = (threadIdx.x >= off) ? s[threadIdx.x - off] : 0;
        __syncthreads();
        s[threadIdx.x] += t;
        __syncthreads();
    }
    g_part[i] = s[threadIdx.x] - v;
    if (threadIdx.x == 255) g_bsum[blockIdx.x] = s[255];
}

// ---------------- GEMM1: h1 = x @ W1 (idx 3 -> ncu-profiled) -----------------
// Each thread owns 2 CONSECUTIVE output cols (2*lane, 2*lane+1): weight fetch
// is one LDS.64 per k instead of two LDS.32 (8 LDS / 32 FMA per k4, was 12).
__global__ void gemm1_kernel(const float* __restrict__ x,
                             const float* __restrict__ W1) {
    __shared__ float sW[DIN * DH];      // 32 KB
    __shared__ float sx[32][DIN];       // 16 KB
    int tid = threadIdx.x;
    for (int i = tid; i < DIN * DH; i += 256) sW[i] = W1[i];
    __syncthreads();
    int warp = tid >> 5, lane = tid & 31;
    int c2 = lane * 2;

    for (int base = blockIdx.x * 32; base < Nn; base += gridDim.x * 32) {
        int r0 = base + warp * 4;
        // stage 4 rows x 128 floats via float4 (each lane: 1 float4 per row)
        #pragma unroll
        for (int r = 0; r < 4; r++) {
            int row = r0 + r;
            if (row < Nn) {
                float4 v = *reinterpret_cast<const float4*>(x + (size_t)row * DIN + lane * 4);
                *reinterpret_cast<float4*>(&sx[warp * 4 + r][lane * 4]) = v;
            }
        }
        __syncwarp();

        float2 acc[4] = {};
        #pragma unroll 8
        for (int k4 = 0; k4 < DIN / 4; k4++) {
            float4 xv[4];
            #pragma unroll
            for (int r = 0; r < 4; r++)
                xv[r] = *reinterpret_cast<const float4*>(&sx[warp * 4 + r][k4 * 4]);
            #pragma unroll
            for (int kk = 0; kk < 4; kk++) {
                int k = k4 * 4 + kk;
                float2 wv = *reinterpret_cast<const float2*>(&sW[k * DH + c2]);
                #pragma unroll
                for (int r = 0; r < 4; r++) {
                    float xs = (kk == 0) ? xv[r].x : (kk == 1) ? xv[r].y : (kk == 2) ? xv[r].z : xv[r].w;
                    acc[r].x = fmaf(xs, wv.x, acc[r].x);
                    acc[r].y = fmaf(xs, wv.y, acc[r].y);
                }
            }
        }

        #pragma unroll
        for (int r = 0; r < 4; r++) {
            int row = r0 + r;
            if (row < Nn)
                *reinterpret_cast<float2*>(g_h1 + (size_t)row * DH + c2) = acc[r];
        }
        __syncwarp();
    }
}

// ---------------- scan B+C merged: each block redundantly scans g_bsum -------
__global__ void scan_bc_kernel() {
    __shared__ int s[256];
    __shared__ int s_off;
    int tid = threadIdx.x;
    int v = (tid < 196) ? g_bsum[tid] : 0;
    s[tid] = v;
    __syncthreads();
    #pragma unroll
    for (int off = 1; off < 256; off <<= 1) {
        int t = (tid >= off) ? s[tid - off] : 0;
        __syncthreads();
        s[tid] += t;
        __syncthreads();
    }
    if (tid == blockIdx.x) s_off = s[tid] - v;   // exclusive prefix of this block
    __syncthreads();
    int i = blockIdx.x * 256 + tid;
    if (i < Nn) {
        int o = g_part[i] + s_off;
        g_row_off[i] = o;
        g_cursor[i] = o;
    }
    if (i == 0) g_row_off[Nn] = Ee;
}

// ---------------- CSR fill: norm computed here -------------------------------
__global__ void fill_kernel() {
    int e = blockIdx.x * blockDim.x + threadIdx.x;
    if (e >= Ee) return;
    int2 sd = g_idx[e];
    float nrm = g_w[e] * g_dinv[sd.x] * g_dinv[sd.y];
    int pos = atomicAdd(&g_cursor[sd.y], 1);
    g_csr[pos] = make_int2(sd.x, __float_as_int(nrm));
}

// ---------------- CSR aggregation (fp32 gather) + fused BN stats -------------
template <int L>
__global__ void agg_kernel(const float* __restrict__ bias) {
    const float* __restrict__ h = (L == 1) ? g_h1 : g_h2;
    float* agg  = (L == 1) ? g_agg1 : g_agg2;
    float* gsum = (L == 1) ? g_sum1 : g_sum2;
    float* gsq  = (L == 1) ? g_sq1  : g_sq2;

    __shared__ int2 stage[8][32];

    int tid = threadIdx.x;
    int w = tid >> 5, lane = tid & 31, half = lane >> 4;
    int l4 = (lane & 15) * 4;
    int wg = (blockIdx.x << 3) + w;
    int nw = gridDim.x << 3;
    float4 bb = *reinterpret_cast<const float4*>(bias + l4);
    float ls0 = 0, ls1 = 0, ls2 = 0, ls3 = 0;
    float lq0 = 0, lq1 = 0, lq2 = 0, lq3 = 0;

    for (int r = wg; r < Nn; r += nw) {
        int beg = g_row_off[r], end = g_row_off[r + 1];
        float4 a0, a1, a2, a3;
        a1 = a2 = a3 = make_float4(0.f, 0.f, 0.f, 0.f);
        if (half == 0) {
            float di = g_dinv[r];
            float sn = di * di;  // self-loop: dinv*1*dinv
            float4 hv = *reinterpret_cast<const float4*>(h + (size_t)r * DH + l4);
            a0 = make_float4(fmaf(hv.x, sn, bb.x), fmaf(hv.y, sn, bb.y),
                             fmaf(hv.z, sn, bb.z), fmaf(hv.w, sn, bb.w));
        } else {
            a0 = make_float4(0.f, 0.f, 0.f, 0.f);
        }

        for (int base = beg; base < end; base += 32) {
            int m = end - base;
            if (m > 32) m = 32;
            stage[w][lane] = (lane < m) ? g_csr[base + lane] : make_int2(0, 0);
            __syncwarp();

            int jj = 0;
            for (; jj + 8 <= m; jj += 8) {
                int2 e0 = stage[w][jj + half];
                int2 e1 = stage[w][jj + 2 + half];
                int2 e2 = stage[w][jj + 4 + half];
                int2 e3 = stage[w][jj + 6 + half];
                float4 v0 = *reinterpret_cast<const float4*>(h + (size_t)e0.x * DH + l4);
                float4 v1 = *reinterpret_cast<const float4*>(h + (size_t)e1.x * DH + l4);
                float4 v2 = *reinterpret_cast<const float4*>(h + (size_t)e2.x * DH + l4);
                float4 v3 = *reinterpret_cast<const float4*>(h + (size_t)e3.x * DH + l4);
                float w0 = __int_as_float(e0.y), w1 = __int_as_float(e1.y);
                float w2 = __int_as_float(e2.y), w3 = __int_as_float(e3.y);
                a0.x = fmaf(v0.x, w0, a0.x); a0.y = fmaf(v0.y, w0, a0.y);
                a0.z = fmaf(v0.z, w0, a0.z); a0.w = fmaf(v0.w, w0, a0.w);
                a1.x = fmaf(v1.x, w1, a1.x); a1.y = fmaf(v1.y, w1, a1.y);
                a1.z = fmaf(v1.z, w1, a1.z); a1.w = fmaf(v1.w, w1, a1.w);
                a2.x = fmaf(v2.x, w2, a2.x); a2.y = fmaf(v2.y, w2, a2.y);
                a2.z = fmaf(v2.z, w2, a2.z); a2.w = fmaf(v2.w, w2, a2.w);
                a3.x = fmaf(v3.x, w3, a3.x); a3.y = fmaf(v3.y, w3, a3.y);
                a3.z = fmaf(v3.z, w3, a3.z); a3.w = fmaf(v3.w, w3, a3.w);
            }
            if (jj < m) {
                int2 e0 = stage[w][jj + half];
                int2 e1 = stage[w][jj + 2 + half];
                int2 e2 = stage[w][jj + 4 + half];
                int2 e3 = stage[w][jj + 6 + half];
                float4 v0 = *reinterpret_cast<const float4*>(h + (size_t)e0.x * DH + l4);
                float4 v1 = *reinterpret_cast<const float4*>(h + (size_t)e1.x * DH + l4);
                float4 v2 = *reinterpret_cast<const float4*>(h + (size_t)e2.x * DH + l4);
                float4 v3 = *reinterpret_cast<const float4*>(h + (size_t)e3.x * DH + l4);
                float w0 = __int_as_float(e0.y), w1 = __int_as_float(e1.y);
                float w2 = __int_as_float(e2.y), w3 = __int_as_float(e3.y);
                a0.x = fmaf(v0.x, w0, a0.x); a0.y = fmaf(v0.y, w0, a0.y);
                a0.z = fmaf(v0.z, w0, a0.z); a0.w = fmaf(v0.w, w0, a0.w);
                a1.x = fmaf(v1.x, w1, a1.x); a1.y = fmaf(v1.y, w1, a1.y);
                a1.z = fmaf(v1.z, w1, a1.z); a1.w = fmaf(v1.w, w1, a1.w);
                a2.x = fmaf(v2.x, w2, a2.x); a2.y = fmaf(v2.y, w2, a2.y);
                a2.z = fmaf(v2.z, w2, a2.z); a2.w = fmaf(v2.w, w2, a2.w);
                a3.x = fmaf(v3.x, w3, a3.x); a3.y = fmaf(v3.y, w3, a3.y);
                a3.z = fmaf(v3.z, w3, a3.z); a3.w = fmaf(v3.w, w3, a3.w);
            }
            __syncwarp();
        }

        float4 acc = make_float4(a0.x + a1.x + a2.x + a3.x,
                                 a0.y + a1.y + a2.y + a3.y,
                                 a0.z + a1.z + a2.z + a3.z,
                                 a0.w + a1.w + a2.w + a3.w);
        acc.x += __shfl_xor_sync(0xffffffffu, acc.x, 16);
        acc.y += __shfl_xor_sync(0xffffffffu, acc.y, 16);
        acc.z += __shfl_xor_sync(0xffffffffu, acc.z, 16);
        acc.w += __shfl_xor_sync(0xffffffffu, acc.w, 16);
        if (half == 0) {
            *reinterpret_cast<float4*>(agg + (size_t)r * DH + l4) = acc;
            ls0 += acc.x; lq0 = fmaf(acc.x, acc.x, lq0);
            ls1 += acc.y; lq1 = fmaf(acc.y, acc.y, lq1);
            ls2 += acc.z; lq2 = fmaf(acc.z, acc.z, lq2);
            ls3 += acc.w; lq3 = fmaf(acc.w, acc.w, lq3);
        }
    }

    __shared__ float ssum[8][64], ssq[8][64];
    if (half == 0) {
        ssum[w][l4 + 0] = ls0; ssum[w][l4 + 1] = ls1;
        ssum[w][l4 + 2] = ls2; ssum[w][l4 + 3] = ls3;
        ssq[w][l4 + 0] = lq0;  ssq[w][l4 + 1] = lq1;
        ssq[w][l4 + 2] = lq2;  ssq[w][l4 + 3] = lq3;
    }
    __syncthreads();
    if (tid < 64) {
        float S = 0.f, Q = 0.f;
        #pragma unroll
        for (int ww = 0; ww < 8; ww++) { S += ssum[ww][tid]; Q += ssq[ww][tid]; }
        atomicAdd(&gsum[tid], S);
        atomicAdd(&gsq[tid], Q);
    }
}

// ---------------- GEMM2: h2 = relu(bn1(agg1)) @ W2 (float2-col layout) -------
__global__ void gemm2_kernel(const float* __restrict__ W2,
                             const float* __restrict__ gamma1,
                             const float* __restrict__ beta1) {
    __shared__ float sW[DH * DH];   // 16 KB
    __shared__ float sx[32][DH];    // 8 KB
    __shared__ float s_scale[DH], s_shift[DH];
    int tid = threadIdx.x;
    if (tid < DH) {
        float mean = g_sum1[tid] * (1.0f / Nn);
        float var = g_sq1[tid] * (1.0f / Nn) - mean * mean;
        float sc = gamma1[tid] * rsqrtf(var + BN_EPS);
        s_scale[tid] = sc;
        s_shift[tid] = fmaf(-mean, sc, beta1[tid]);
    }
    for (int i = tid; i < DH * DH; i += 256) sW[i] = W2[i];
    __syncthreads();
    int warp = tid >> 5, lane = tid & 31;
    int c2 = lane * 2;

    for (int base = blockIdx.x * 32; base < Nn; base += gridDim.x * 32) {
        int r0 = base + warp * 4;
        #pragma unroll
        for (int r = 0; r < 4; r++) {
            int row = r0 + r;
            if (row < Nn) {
                // stage with fused BN+ReLU; float2 per lane covers 64 cols
                float2 v = *reinterpret_cast<const float2*>(g_agg1 + (size_t)row * DH + c2);
                float2 o;
                o.x = fmaxf(fmaf(v.x, s_scale[c2], s_shift[c2]), 0.f);
                o.y = fmaxf(fmaf(v.y, s_scale[c2 + 1], s_shift[c2 + 1]), 0.f);
                *reinterpret_cast<float2*>(&sx[warp * 4 + r][c2]) = o;
            }
        }
        __syncwarp();

        float2 acc[4] = {};
        #pragma unroll 4
        for (int k4 = 0; k4 < DH / 4; k4++) {
            float4 xv[4];
            #pragma unroll
            for (int r = 0; r < 4; r++)
                xv[r] = *reinterpret_cast<const float4*>(&sx[warp * 4 + r][k4 * 4]);
            #pragma unroll
            for (int kk = 0; kk < 4; kk++) {
                int k = k4 * 4 + kk;
                float2 wv = *reinterpret_cast<const float2*>(&sW[k * DH + c2]);
                #pragma unroll
                for (int r = 0; r < 4; r++) {
                    float xs = (kk == 0) ? xv[r].x : (kk == 1) ? xv[r].y : (kk == 2) ? xv[r].z : xv[r].w;
                    acc[r].x = fmaf(xs, wv.x, acc[r].x);
                    acc[r].y = fmaf(xs, wv.y, acc[r].y);
                }
            }
        }

        #pragma unroll
        for (int r = 0; r < 4; r++) {
            int row = r0 + r;
            if (row < Nn)
                *reinterpret_cast<float2*>(g_h2 + (size_t)row * DH + c2) = acc[r];
        }
        __syncwarp();
    }
}

// ---------------- final: out = relu(bn2(agg2)) -------------------------------
__global__ void final_kernel(const float* __restrict__ gamma2,
                             const float* __restrict__ beta2,
                             float* __restrict__ out) {
    __shared__ float s_scale[DH], s_shift[DH];
    int tid = threadIdx.x;
    if (tid < DH) {
        float mean = g_sum2[tid] * (1.0f / Nn);
        float var = g_sq2[tid] * (1.0f / Nn) - mean * mean;
        float sc = gamma2[tid] * rsqrtf(var + BN_EPS);
        s_scale[tid] = sc;
        s_shift[tid] = fmaf(-mean, sc, beta2[tid]);
    }
    __syncthreads();
    int i = blockIdx.x * 256 + tid;
    if (i < Nn * DH) {
        int c = i & 63;
        out[i] = fmaxf(fmaf(g_agg2[i], s_scale[c], s_shift[c]), 0.f);
    }
}

// -----------------------------------------------------------------------------
extern "C" void kernel_launch(void* const* d_in, const int* in_sizes, int n_in,
                              void* d_out, int out_size) {
    const float* x      = (const float*)d_in[0];
    const void*  ei_sc  = d_in[1];
    const float* w_sc   = (const float*)d_in[2];
    // d_in[3] = edge_index_fc (unused by reference)
    const float* w_fc   = (const float*)d_in[4];
    const float* alpha  = (const float*)d_in[5];
    const float* W1     = (const float*)d_in[6];
    const float* b1     = (const float*)d_in[7];
    const float* W2     = (const float*)d_in[8];
    const float* b2     = (const float*)d_in[9];
    const float* gamma1 = (const float*)d_in[10];
    const float* beta1  = (const float*)d_in[11];
    const float* gamma2 = (const float*)d_in[12];
    const float* beta2  = (const float*)d_in[13];
    float* out = (float*)d_out;

    const int TB = 256;
    const int nblkE = (Ee + TB - 1) / TB;       // 6250

    // gemm1 kept at launch idx 3: harness ncu consistently profiles idx 3.
    init_kernel<<<196, TB>>>(alpha);                          // idx 0
    mix_deg_kernel<<<nblkE, TB>>>(ei_sc, w_sc, w_fc);         // idx 1
    scan_a_kernel<<<196, TB>>>();                             // idx 2
    gemm1_kernel<<<592, TB>>>(x, W1);                         // idx 3  <- profiled
    scan_bc_kernel<<<196, TB>>>();                            // idx 4
    fill_kernel<<<nblkE, TB>>>();                             // idx 5
    agg_kernel<1><<<592, TB>>>(b1);                           // idx 6
    gemm2_kernel<<<592, TB>>>(W2, gamma1, beta1);             // idx 7
    agg_kernel<2><<<592, TB>>>(b2);                           // idx 8
    final_kernel<<<(Nn * DH + TB - 1) / TB, TB>>>(gamma2, beta2, out);  // idx 9
}

// round 14
// speedup vs baseline: 1.2044x; 1.0073x over previous
#include <cuda_runtime.h>
#include <math.h>

#define Nn 50000
#define Ee 1600000
#define DIN 128
#define DH 64
#define BN_EPS 1e-5f

// ---------------- scratch (device globals; no allocation allowed) -------------
__device__ float  g_w[Ee];            // mixed weight (pre-norm)
__device__ int2   g_idx[Ee];          // (src, dst) as int32
__device__ int2   g_csr[Ee];          // dst-sorted: (src, bitcast(norm))
__device__ float2 g_degcnt[Nn];       // (weighted degree incl self, count) via red.v2
__device__ float  g_dinv[Nn];         // rsqrt(deg)
__device__ int    g_part[50176];      // block-local exclusive scan
__device__ int    g_bsum[196];
__device__ int    g_row_off[Nn + 1];  // CSR row offsets
__device__ int    g_cursor[Nn];       // fill cursors
__device__ float  g_h1[Nn * DH];      // x @ W1  (fp32: agg is issue-bound; fp16 was slower)
__device__ float  g_h2[Nn * DH];
__device__ float  g_agg1[Nn * DH];
__device__ float  g_agg2[Nn * DH];
__device__ float  g_sum1[DH], g_sq1[DH], g_sum2[DH], g_sq2[DH];
__device__ float  g_a;

// ---------------- init: deg=(1,0) self-loop, BN stats, sigmoid(alpha) --------
__global__ void init_kernel(const float* __restrict__ alpha) {
    int i = blockIdx.x * blockDim.x + threadIdx.x;
    if (i < Nn) g_degcnt[i] = make_float2(1.0f, 0.0f);
    if (i < DH) { g_sum1[i] = 0.f; g_sq1[i] = 0.f; g_sum2[i] = 0.f; g_sq2[i] = 0.f; }
    if (i == 0) g_a = 1.0f / (1.0f + expf(-alpha[0]));
}

// ---------------- mix weights, record (src,dst), fused degree+count red ------
__global__ void mix_deg_kernel(const void* __restrict__ ei,
                               const float* __restrict__ wsc,
                               const float* __restrict__ wfc) {
    int tid = threadIdx.x;
    int any = __syncthreads_or((int)((const unsigned*)ei)[2 * tid + 1]);
    int is64 = (any == 0);
    int e = blockIdx.x * blockDim.x + tid;
    if (e >= Ee) return;
    int s, d;
    if (is64) {
        const long long* p = (const long long*)ei;   // full-8B loads: full sectors
        s = (int)p[e];
        d = (int)p[(size_t)Ee + e];
    } else {
        const int* p = (const int*)ei;
        s = p[e];
        d = p[Ee + e];
    }
    float a = g_a;
    float w = a * wsc[e] + (1.0f - a) * wfc[e];
    g_w[e] = w;
    g_idx[e] = make_int2(s, d);
    float* dp = (float*)&g_degcnt[d];
    asm volatile("red.global.add.v2.f32 [%0], {%1,%2};"
                 :: "l"(dp), "f"(w), "f"(1.0f) : "memory");
}

// ---------------- scan part A (+ dinv fused) ---------------------------------
__global__ void scan_a_kernel() {
    __shared__ int s[256];
    int i = blockIdx.x * 256 + threadIdx.x;
    int v = 0;
    if (i < Nn) {
        float2 dc = g_degcnt[i];
        v = (int)dc.y;
        g_dinv[i] = (dc.x > 0.f) ? rsqrtf(fmaxf(dc.x, 1e-12f)) : 0.f;
    }
    s[threadIdx.x] = v;
    __syncthreads();
    #pragma unroll
    for (int off = 1; off < 256; off <<= 1) {
        int t = (threadIdx.x >= off) ? s[threadIdx.x - off] : 0;
        __syncthreads();
        s[threadIdx.x] += t;
        __syncthreads();
    }
    g_part[i] = s[threadIdx.x] - v;
    if (threadIdx.x == 255) g_bsum[blockIdx.x] = s[255];
}

// ---------------- GEMM1: h1 = x @ W1 (runs on forked stream) -----------------
__global__ void gemm1_kernel(const float* __restrict__ x,
                             const float* __restrict__ W1) {
    __shared__ float sW[DIN * DH];      // 32 KB
    __shared__ float sx[32][DIN];       // 16 KB
    int tid = threadIdx.x;
    for (int i = tid; i < DIN * DH; i += 256) sW[i] = W1[i];
    __syncthreads();
    int warp = tid >> 5, lane = tid & 31;
    int c2 = lane * 2;

    for (int base = blockIdx.x * 32; base < Nn; base += gridDim.x * 32) {
        int r0 = base + warp * 4;
        #pragma unroll
        for (int r = 0; r < 4; r++) {
            int row = r0 + r;
            if (row < Nn) {
                float4 v = *reinterpret_cast<const float4*>(x + (size_t)row * DIN + lane * 4);
                *reinterpret_cast<float4*>(&sx[warp * 4 + r][lane * 4]) = v;
            }
        }
        __syncwarp();

        float2 acc[4] = {};
        #pragma unroll 8
        for (int k4 = 0; k4 < DIN / 4; k4++) {
            float4 xv[4];
            #pragma unroll
            for (int r = 0; r < 4; r++)
                xv[r] = *reinterpret_cast<const float4*>(&sx[warp * 4 + r][k4 * 4]);
            #pragma unroll
            for (int kk = 0; kk < 4; kk++) {
                int k = k4 * 4 + kk;
                float2 wv = *reinterpret_cast<const float2*>(&sW[k * DH + c2]);
                #pragma unroll
                for (int r = 0; r < 4; r++) {
                    float xs = (kk == 0) ? xv[r].x : (kk == 1) ? xv[r].y : (kk == 2) ? xv[r].z : xv[r].w;
                    acc[r].x = fmaf(xs, wv.x, acc[r].x);
                    acc[r].y = fmaf(xs, wv.y, acc[r].y);
                }
            }
        }

        #pragma unroll
        for (int r = 0; r < 4; r++) {
            int row = r0 + r;
            if (row < Nn)
                *reinterpret_cast<float2*>(g_h1 + (size_t)row * DH + c2) = acc[r];
        }
        __syncwarp();
    }
}

// ---------------- scan B+C merged: each block redundantly scans g_bsum -------
__global__ void scan_bc_kernel() {
    __shared__ int s[256];
    __shared__ int s_off;
    int tid = threadIdx.x;
    int v = (tid < 196) ? g_bsum[tid] : 0;
    s[tid] = v;
    __syncthreads();
    #pragma unroll
    for (int off = 1; off < 256; off <<= 1) {
        int t = (tid >= off) ? s[tid - off] : 0;
        __syncthreads();
        s[tid] += t;
        __syncthreads();
    }
    if (tid == blockIdx.x) s_off = s[tid] - v;   // exclusive prefix of this block
    __syncthreads();
    int i = blockIdx.x * 256 + tid;
    if (i < Nn) {
        int o = g_part[i] + s_off;
        g_row_off[i] = o;
        g_cursor[i] = o;
    }
    if (i == 0) g_row_off[Nn] = Ee;
}

// ---------------- CSR fill: norm computed here -------------------------------
__global__ void fill_kernel() {
    int e = blockIdx.x * blockDim.x + threadIdx.x;
    if (e >= Ee) return;
    int2 sd = g_idx[e];
    float nrm = g_w[e] * g_dinv[sd.x] * g_dinv[sd.y];
    int pos = atomicAdd(&g_cursor[sd.y], 1);
    g_csr[pos] = make_int2(sd.x, __float_as_int(nrm));
}

// ---------------- CSR aggregation (fp32 gather) + fused BN stats -------------
template <int L>
__global__ void agg_kernel(const float* __restrict__ bias) {
    const float* __restrict__ h = (L == 1) ? g_h1 : g_h2;
    float* agg  = (L == 1) ? g_agg1 : g_agg2;
    float* gsum = (L == 1) ? g_sum1 : g_sum2;
    float* gsq  = (L == 1) ? g_sq1  : g_sq2;

    __shared__ int2 stage[8][32];

    int tid = threadIdx.x;
    int w = tid >> 5, lane = tid & 31, half = lane >> 4;
    int l4 = (lane & 15) * 4;
    int wg = (blockIdx.x << 3) + w;
    int nw = gridDim.x << 3;
    float4 bb = *reinterpret_cast<const float4*>(bias + l4);
    float ls0 = 0, ls1 = 0, ls2 = 0, ls3 = 0;
    float lq0 = 0, lq1 = 0, lq2 = 0, lq3 = 0;

    for (int r = wg; r < Nn; r += nw) {
        int beg = g_row_off[r], end = g_row_off[r + 1];
        float4 a0, a1, a2, a3;
        a1 = a2 = a3 = make_float4(0.f, 0.f, 0.f, 0.f);
        if (half == 0) {
            float di = g_dinv[r];
            float sn = di * di;  // self-loop: dinv*1*dinv
            float4 hv = *reinterpret_cast<const float4*>(h + (size_t)r * DH + l4);
            a0 = make_float4(fmaf(hv.x, sn, bb.x), fmaf(hv.y, sn, bb.y),
                             fmaf(hv.z, sn, bb.z), fmaf(hv.w, sn, bb.w));
        } else {
            a0 = make_float4(0.f, 0.f, 0.f, 0.f);
        }

        for (int base = beg; base < end; base += 32) {
            int m = end - base;
            if (m > 32) m = 32;
            stage[w][lane] = (lane < m) ? g_csr[base + lane] : make_int2(0, 0);
            __syncwarp();

            int jj = 0;
            for (; jj + 8 <= m; jj += 8) {
                int2 e0 = stage[w][jj + half];
                int2 e1 = stage[w][jj + 2 + half];
                int2 e2 = stage[w][jj + 4 + half];
                int2 e3 = stage[w][jj + 6 + half];
                float4 v0 = *reinterpret_cast<const float4*>(h + (size_t)e0.x * DH + l4);
                float4 v1 = *reinterpret_cast<const float4*>(h + (size_t)e1.x * DH + l4);
                float4 v2 = *reinterpret_cast<const float4*>(h + (size_t)e2.x * DH + l4);
                float4 v3 = *reinterpret_cast<const float4*>(h + (size_t)e3.x * DH + l4);
                float w0 = __int_as_float(e0.y), w1 = __int_as_float(e1.y);
                float w2 = __int_as_float(e2.y), w3 = __int_as_float(e3.y);
                a0.x = fmaf(v0.x, w0, a0.x); a0.y = fmaf(v0.y, w0, a0.y);
                a0.z = fmaf(v0.z, w0, a0.z); a0.w = fmaf(v0.w, w0, a0.w);
                a1.x = fmaf(v1.x, w1, a1.x); a1.y = fmaf(v1.y, w1, a1.y);
                a1.z = fmaf(v1.z, w1, a1.z); a1.w = fmaf(v1.w, w1, a1.w);
                a2.x = fmaf(v2.x, w2, a2.x); a2.y = fmaf(v2.y, w2, a2.y);
                a2.z = fmaf(v2.z, w2, a2.z); a2.w = fmaf(v2.w, w2, a2.w);
                a3.x = fmaf(v3.x, w3, a3.x); a3.y = fmaf(v3.y, w3, a3.y);
                a3.z = fmaf(v3.z, w3, a3.z); a3.w = fmaf(v3.w, w3, a3.w);
            }
            if (jj < m) {
                int2 e0 = stage[w][jj + half];
                int2 e1 = stage[w][jj + 2 + half];
                int2 e2 = stage[w][jj + 4 + half];
                int2 e3 = stage[w][jj + 6 + half];
                float4 v0 = *reinterpret_cast<const float4*>(h + (size_t)e0.x * DH + l4);
                float4 v1 = *reinterpret_cast<const float4*>(h + (size_t)e1.x * DH + l4);
                float4 v2 = *reinterpret_cast<const float4*>(h + (size_t)e2.x * DH + l4);
                float4 v3 = *reinterpret_cast<const float4*>(h + (size_t)e3.x * DH + l4);
                float w0 = __int_as_float(e0.y), w1 = __int_as_float(e1.y);
                float w2 = __int_as_float(e2.y), w3 = __int_as_float(e3.y);
                a0.x = fmaf(v0.x, w0, a0.x); a0.y = fmaf(v0.y, w0, a0.y);
                a0.z = fmaf(v0.z, w0, a0.z); a0.w = fmaf(v0.w, w0, a0.w);
                a1.x = fmaf(v1.x, w1, a1.x); a1.y = fmaf(v1.y, w1, a1.y);
                a1.z = fmaf(v1.z, w1, a1.z); a1.w = fmaf(v1.w, w1, a1.w);
                a2.x = fmaf(v2.x, w2, a2.x); a2.y = fmaf(v2.y, w2, a2.y);
                a2.z = fmaf(v2.z, w2, a2.z); a2.w = fmaf(v2.w, w2, a2.w);
                a3.x = fmaf(v3.x, w3, a3.x); a3.y = fmaf(v3.y, w3, a3.y);
                a3.z = fmaf(v3.z, w3, a3.z); a3.w = fmaf(v3.w, w3, a3.w);
            }
            __syncwarp();
        }

        float4 acc = make_float4(a0.x + a1.x + a2.x + a3.x,
                                 a0.y + a1.y + a2.y + a3.y,
                                 a0.z + a1.z + a2.z + a3.z,
                                 a0.w + a1.w + a2.w + a3.w);
        acc.x += __shfl_xor_sync(0xffffffffu, acc.x, 16);
        acc.y += __shfl_xor_sync(0xffffffffu, acc.y, 16);
        acc.z += __shfl_xor_sync(0xffffffffu, acc.z, 16);
        acc.w += __shfl_xor_sync(0xffffffffu, acc.w, 16);
        if (half == 0) {
            *reinterpret_cast<float4*>(agg + (size_t)r * DH + l4) = acc;
            ls0 += acc.x; lq0 = fmaf(acc.x, acc.x, lq0);
            ls1 += acc.y; lq1 = fmaf(acc.y, acc.y, lq1);
            ls2 += acc.z; lq2 = fmaf(acc.z, acc.z, lq2);
            ls3 += acc.w; lq3 = fmaf(acc.w, acc.w, lq3);
        }
    }

    __shared__ float ssum[8][64], ssq[8][64];
    if (half == 0) {
        ssum[w][l4 + 0] = ls0; ssum[w][l4 + 1] = ls1;
        ssum[w][l4 + 2] = ls2; ssum[w][l4 + 3] = ls3;
        ssq[w][l4 + 0] = lq0;  ssq[w][l4 + 1] = lq1;
        ssq[w][l4 + 2] = lq2;  ssq[w][l4 + 3] = lq3;
    }
    __syncthreads();
    if (tid < 64) {
        float S = 0.f, Q = 0.f;
        #pragma unroll
        for (int ww = 0; ww < 8; ww++) { S += ssum[ww][tid]; Q += ssq[ww][tid]; }
        atomicAdd(&gsum[tid], S);
        atomicAdd(&gsq[tid], Q);
    }
}

// ---------------- GEMM2: h2 = relu(bn1(agg1)) @ W2 (float2-col layout) -------
__global__ void gemm2_kernel(const float* __restrict__ W2,
                             const float* __restrict__ gamma1,
                             const float* __restrict__ beta1) {
    __shared__ float sW[DH * DH];   // 16 KB
    __shared__ float sx[32][DH];    // 8 KB
    __shared__ float s_scale[DH], s_shift[DH];
    int tid = threadIdx.x;
    if (tid < DH) {
        float mean = g_sum1[tid] * (1.0f / Nn);
        float var = g_sq1[tid] * (1.0f / Nn) - mean * mean;
        float sc = gamma1[tid] * rsqrtf(var + BN_EPS);
        s_scale[tid] = sc;
        s_shift[tid] = fmaf(-mean, sc, beta1[tid]);
    }
    for (int i = tid; i < DH * DH; i += 256) sW[i] = W2[i];
    __syncthreads();
    int warp = tid >> 5, lane = tid & 31;
    int c2 = lane * 2;

    for (int base = blockIdx.x * 32; base < Nn; base += gridDim.x * 32) {
        int r0 = base + warp * 4;
        #pragma unroll
        for (int r = 0; r < 4; r++) {
            int row = r0 + r;
            if (row < Nn) {
                float2 v = *reinterpret_cast<const float2*>(g_agg1 + (size_t)row * DH + c2);
                float2 o;
                o.x = fmaxf(fmaf(v.x, s_scale[c2], s_shift[c2]), 0.f);
                o.y = fmaxf(fmaf(v.y, s_scale[c2 + 1], s_shift[c2 + 1]), 0.f);
                *reinterpret_cast<float2*>(&sx[warp * 4 + r][c2]) = o;
            }
        }
        __syncwarp();

        float2 acc[4] = {};
        #pragma unroll 4
        for (int k4 = 0; k4 < DH / 4; k4++) {
            float4 xv[4];
            #pragma unroll
            for (int r = 0; r < 4; r++)
                xv[r] = *reinterpret_cast<const float4*>(&sx[warp * 4 + r][k4 * 4]);
            #pragma unroll
            for (int kk = 0; kk < 4; kk++) {
                int k = k4 * 4 + kk;
                float2 wv = *reinterpret_cast<const float2*>(&sW[k * DH + c2]);
                #pragma unroll
                for (int r = 0; r < 4; r++) {
                    float xs = (kk == 0) ? xv[r].x : (kk == 1) ? xv[r].y : (kk == 2) ? xv[r].z : xv[r].w;
                    acc[r].x = fmaf(xs, wv.x, acc[r].x);
                    acc[r].y = fmaf(xs, wv.y, acc[r].y);
                }
            }
        }

        #pragma unroll
        for (int r = 0; r < 4; r++) {
            int row = r0 + r;
            if (row < Nn)
                *reinterpret_cast<float2*>(g_h2 + (size_t)row * DH + c2) = acc[r];
        }
        __syncwarp();
    }
}

// ---------------- final: out = relu(bn2(agg2)) -------------------------------
__global__ void final_kernel(const float* __restrict__ gamma2,
                             const float* __restrict__ beta2,
                             float* __restrict__ out) {
    __shared__ float s_scale[DH], s_shift[DH];
    int tid = threadIdx.x;
    if (tid < DH) {
        float mean = g_sum2[tid] * (1.0f / Nn);
        float var = g_sq2[tid] * (1.0f / Nn) - mean * mean;
        float sc = gamma2[tid] * rsqrtf(var + BN_EPS);
        s_scale[tid] = sc;
        s_shift[tid] = fmaf(-mean, sc, beta2[tid]);
    }
    __syncthreads();
    int i = blockIdx.x * 256 + tid;
    if (i < Nn * DH) {
        int c = i & 63;
        out[i] = fmaxf(fmaf(g_agg2[i], s_scale[c], s_shift[c]), 0.f);
    }
}

// -----------------------------------------------------------------------------
extern "C" void kernel_launch(void* const* d_in, const int* in_sizes, int n_in,
                              void* d_out, int out_size) {
    const float* x      = (const float*)d_in[0];
    const void*  ei_sc  = d_in[1];
    const float* w_sc   = (const float*)d_in[2];
    // d_in[3] = edge_index_fc (unused by reference)
    const float* w_fc   = (const float*)d_in[4];
    const float* alpha  = (const float*)d_in[5];
    const float* W1     = (const float*)d_in[6];
    const float* b1     = (const float*)d_in[7];
    const float* W2     = (const float*)d_in[8];
    const float* b2     = (const float*)d_in[9];
    const float* gamma1 = (const float*)d_in[10];
    const float* beta1  = (const float*)d_in[11];
    const float* gamma2 = (const float*)d_in[12];
    const float* beta2  = (const float*)d_in[13];
    float* out = (float*)d_out;

    const int TB = 256;
    const int nblkE = (Ee + TB - 1) / TB;       // 6250

    // Fork: gemm1 (independent of the edge prologue) runs on the per-thread
    // stream, joined back before agg1. Event record/wait inside stream capture
    // become graph edges; no device memory is allocated (events are host
    // objects, intentionally not destroyed to avoid destroy-during-capture).
    cudaEvent_t ev_fork, ev_join;
    cudaEventCreateWithFlags(&ev_fork, cudaEventDisableTiming);
    cudaEventCreateWithFlags(&ev_join, cudaEventDisableTiming);
    cudaStream_t s2 = cudaStreamPerThread;

    cudaEventRecord(ev_fork, 0);                 // fork from capture stream
    cudaStreamWaitEvent(s2, ev_fork, 0);
    gemm1_kernel<<<592, TB, 0, s2>>>(x, W1);     // overlaps prologue below
    cudaEventRecord(ev_join, s2);

    init_kernel<<<196, TB>>>(alpha);
    mix_deg_kernel<<<nblkE, TB>>>(ei_sc, w_sc, w_fc);
    scan_a_kernel<<<196, TB>>>();
    scan_bc_kernel<<<196, TB>>>();
    fill_kernel<<<nblkE, TB>>>();

    cudaStreamWaitEvent(0, ev_join, 0);          // join: agg1 needs g_h1
    agg_kernel<1><<<592, TB>>>(b1);
    gemm2_kernel<<<592, TB>>>(W2, gamma1, beta1);
    agg_kernel<2><<<592, TB>>>(b2);
    final_kernel<<<(Nn * DH + TB - 1) / TB, TB>>>(gamma2, beta2, out);
}

// round 15
// speedup vs baseline: 1.2297x; 1.0210x over previous
#include <cuda_runtime.h>
#include <math.h>

#define Nn 50000
#define Ee 1600000
#define DIN 128
#define DH 64
#define BN_EPS 1e-5f

// ---------------- scratch (device globals; no allocation allowed) -------------
__device__ float  g_w[Ee];            // mixed weight (pre-norm)
__device__ int2   g_idx[Ee];          // (src, dst) as int32
__device__ int2   g_csr[Ee];          // dst-sorted: (src, bitcast(norm))
__device__ float2 g_degcnt[Nn];       // (weighted degree incl self, count) via red.v2
__device__ float  g_dinv[Nn];         // rsqrt(deg)
__device__ int    g_part[50176];      // block-local exclusive scan
__device__ int    g_bsum[196];
__device__ int    g_row_off[Nn + 1];  // CSR row offsets
__device__ int    g_cursor[Nn];       // fill cursors
__device__ float  g_h1[Nn * DH];      // x @ W1  (fp32: agg is issue-bound; fp16 was slower)
__device__ float  g_h2[Nn * DH];
__device__ float  g_agg1[Nn * DH];
__device__ float  g_agg2[Nn * DH];
__device__ float  g_sum1[DH], g_sq1[DH], g_sum2[DH], g_sq2[DH];
__device__ float  g_a;

// ---------------- init: deg=(1,0) self-loop, BN stats, sigmoid(alpha) --------
__global__ void init_kernel(const float* __restrict__ alpha) {
    int i = blockIdx.x * blockDim.x + threadIdx.x;
    if (i < Nn) g_degcnt[i] = make_float2(1.0f, 0.0f);
    if (i < DH) { g_sum1[i] = 0.f; g_sq1[i] = 0.f; g_sum2[i] = 0.f; g_sq2[i] = 0.f; }
    if (i == 0) g_a = 1.0f / (1.0f + expf(-alpha[0]));
}

// ---------------- mix weights, record (src,dst), fused degree+count red ------
__global__ void mix_deg_kernel(const void* __restrict__ ei,
                               const float* __restrict__ wsc,
                               const float* __restrict__ wfc) {
    int tid = threadIdx.x;
    int any = __syncthreads_or((int)((const unsigned*)ei)[2 * tid + 1]);
    int is64 = (any == 0);
    int e = blockIdx.x * blockDim.x + tid;
    if (e >= Ee) return;
    int s, d;
    if (is64) {
        const long long* p = (const long long*)ei;   // full-8B loads: full sectors
        s = (int)p[e];
        d = (int)p[(size_t)Ee + e];
    } else {
        const int* p = (const int*)ei;
        s = p[e];
        d = p[Ee + e];
    }
    float a = g_a;
    float w = a * wsc[e] + (1.0f - a) * wfc[e];
    g_w[e] = w;
    g_idx[e] = make_int2(s, d);
    float* dp = (float*)&g_degcnt[d];
    asm volatile("red.global.add.v2.f32 [%0], {%1,%2};"
                 :: "l"(dp), "f"(w), "f"(1.0f) : "memory");
}

// ---------------- scan part A (+ dinv fused) ---------------------------------
__global__ void scan_a_kernel() {
    __shared__ int s[256];
    int i = blockIdx.x * 256 + threadIdx.x;
    int v = 0;
    if (i < Nn) {
        float2 dc = g_degcnt[i];
        v = (int)dc.y;
        g_dinv[i] = (dc.x > 0.f) ? rsqrtf(fmaxf(dc.x, 1e-12f)) : 0.f;
    }
    s[threadIdx.x] = v;
    __syncthreads();
    #pragma unroll
    for (int off = 1; off < 256; off <<= 1) {
        int t = (threadIdx.x >= off) ? s[threadIdx.x - off] : 0;
        __syncthreads();
        s[threadIdx.x] += t;
        __syncthreads();
    }
    g_part[i] = s[threadIdx.x] - v;
    if (threadIdx.x == 255) g_bsum[blockIdx.x] = s[255];
}

// ---------------- GEMM1: h1 = x @ W1 (runs on forked non-blocking stream) ----
__global__ void gemm1_kernel(const float* __restrict__ x,
                             const float* __restrict__ W1) {
    __shared__ float sW[DIN * DH];      // 32 KB
    __shared__ float sx[32][DIN];       // 16 KB
    int tid = threadIdx.x;
    for (int i = tid; i < DIN * DH; i += 256) sW[i] = W1[i];
    __syncthreads();
    int warp = tid >> 5, lane = tid & 31;
    int c2 = lane * 2;

    for (int base = blockIdx.x * 32; base < Nn; base += gridDim.x * 32) {
        int r0 = base + warp * 4;
        #pragma unroll
        for (int r = 0; r < 4; r++) {
            int row = r0 + r;
            if (row < Nn) {
                float4 v = *reinterpret_cast<const float4*>(x + (size_t)row * DIN + lane * 4);
                *reinterpret_cast<float4*>(&sx[warp * 4 + r][lane * 4]) = v;
            }
        }
        __syncwarp();

        float2 acc[4] = {};
        #pragma unroll 8
        for (int k4 = 0; k4 < DIN / 4; k4++) {
            float4 xv[4];
            #pragma unroll
            for (int r = 0; r < 4; r++)
                xv[r] = *reinterpret_cast<const float4*>(&sx[warp * 4 + r][k4 * 4]);
            #pragma unroll
            for (int kk = 0; kk < 4; kk++) {
                int k = k4 * 4 + kk;
                float2 wv = *reinterpret_cast<const float2*>(&sW[k * DH + c2]);
                #pragma unroll
                for (int r = 0; r < 4; r++) {
                    float xs = (kk == 0) ? xv[r].x : (kk == 1) ? xv[r].y : (kk == 2) ? xv[r].z : xv[r].w;
                    acc[r].x = fmaf(xs, wv.x, acc[r].x);
                    acc[r].y = fmaf(xs, wv.y, acc[r].y);
                }
            }
        }

        #pragma unroll
        for (int r = 0; r < 4; r++) {
            int row = r0 + r;
            if (row < Nn)
                *reinterpret_cast<float2*>(g_h1 + (size_t)row * DH + c2) = acc[r];
        }
        __syncwarp();
    }
}

// ---------------- scan B+C merged: each block redundantly scans g_bsum -------
__global__ void scan_bc_kernel() {
    __shared__ int s[256];
    __shared__ int s_off;
    int tid = threadIdx.x;
    int v = (tid < 196) ? g_bsum[tid] : 0;
    s[tid] = v;
    __syncthreads();
    #pragma unroll
    for (int off = 1; off < 256; off <<= 1) {
        int t = (tid >= off) ? s[tid - off] : 0;
        __syncthreads();
        s[tid] += t;
        __syncthreads();
    }
    if (tid == blockIdx.x) s_off = s[tid] - v;   // exclusive prefix of this block
    __syncthreads();
    int i = blockIdx.x * 256 + tid;
    if (i < Nn) {
        int o = g_part[i] + s_off;
        g_row_off[i] = o;
        g_cursor[i] = o;
    }
    if (i == 0) g_row_off[Nn] = Ee;
}

// ---------------- CSR fill: norm computed here -------------------------------
__global__ void fill_kernel() {
    int e = blockIdx.x * blockDim.x + threadIdx.x;
    if (e >= Ee) return;
    int2 sd = g_idx[e];
    float nrm = g_w[e] * g_dinv[sd.x] * g_dinv[sd.y];
    int pos = atomicAdd(&g_cursor[sd.y], 1);
    g_csr[pos] = make_int2(sd.x, __float_as_int(nrm));
}

// ---------------- CSR aggregation (fp32 gather) + fused BN stats -------------
template <int L>
__global__ void agg_kernel(const float* __restrict__ bias) {
    const float* __restrict__ h = (L == 1) ? g_h1 : g_h2;
    float* agg  = (L == 1) ? g_agg1 : g_agg2;
    float* gsum = (L == 1) ? g_sum1 : g_sum2;
    float* gsq  = (L == 1) ? g_sq1  : g_sq2;

    __shared__ int2 stage[8][32];

    int tid = threadIdx.x;
    int w = tid >> 5, lane = tid & 31, half = lane >> 4;
    int l4 = (lane & 15) * 4;
    int wg = (blockIdx.x << 3) + w;
    int nw = gridDim.x << 3;
    float4 bb = *reinterpret_cast<const float4*>(bias + l4);
    float ls0 = 0, ls1 = 0, ls2 = 0, ls3 = 0;
    float lq0 = 0, lq1 = 0, lq2 = 0, lq3 = 0;

    for (int r = wg; r < Nn; r += nw) {
        int beg = g_row_off[r], end = g_row_off[r + 1];
        float4 a0, a1, a2, a3;
        a1 = a2 = a3 = make_float4(0.f, 0.f, 0.f, 0.f);
        if (half == 0) {
            float di = g_dinv[r];
            float sn = di * di;  // self-loop: dinv*1*dinv
            float4 hv = *reinterpret_cast<const float4*>(h + (size_t)r * DH + l4);
            a0 = make_float4(fmaf(hv.x, sn, bb.x), fmaf(hv.y, sn, bb.y),
                             fmaf(hv.z, sn, bb.z), fmaf(hv.w, sn, bb.w));
        } else {
            a0 = make_float4(0.f, 0.f, 0.f, 0.f);
        }

        for (int base = beg; base < end; base += 32) {
            int m = end - base;
            if (m > 32) m = 32;
            stage[w][lane] = (lane < m) ? g_csr[base + lane] : make_int2(0, 0);
            __syncwarp();

            int jj = 0;
            for (; jj + 8 <= m; jj += 8) {
                int2 e0 = stage[w][jj + half];
                int2 e1 = stage[w][jj + 2 + half];
                int2 e2 = stage[w][jj + 4 + half];
                int2 e3 = stage[w][jj + 6 + half];
                float4 v0 = *reinterpret_cast<const float4*>(h + (size_t)e0.x * DH + l4);
                float4 v1 = *reinterpret_cast<const float4*>(h + (size_t)e1.x * DH + l4);
                float4 v2 = *reinterpret_cast<const float4*>(h + (size_t)e2.x * DH + l4);
                float4 v3 = *reinterpret_cast<const float4*>(h + (size_t)e3.x * DH + l4);
                float w0 = __int_as_float(e0.y), w1 = __int_as_float(e1.y);
                float w2 = __int_as_float(e2.y), w3 = __int_as_float(e3.y);
                a0.x = fmaf(v0.x, w0, a0.x); a0.y = fmaf(v0.y, w0, a0.y);
                a0.z = fmaf(v0.z, w0, a0.z); a0.w = fmaf(v0.w, w0, a0.w);
                a1.x = fmaf(v1.x, w1, a1.x); a1.y = fmaf(v1.y, w1, a1.y);
                a1.z = fmaf(v1.z, w1, a1.z); a1.w = fmaf(v1.w, w1, a1.w);
                a2.x = fmaf(v2.x, w2, a2.x); a2.y = fmaf(v2.y, w2, a2.y);
                a2.z = fmaf(v2.z, w2, a2.z); a2.w = fmaf(v2.w, w2, a2.w);
                a3.x = fmaf(v3.x, w3, a3.x); a3.y = fmaf(v3.y, w3, a3.y);
                a3.z = fmaf(v3.z, w3, a3.z); a3.w = fmaf(v3.w, w3, a3.w);
            }
            if (jj < m) {
                int2 e0 = stage[w][jj + half];
                int2 e1 = stage[w][jj + 2 + half];
                int2 e2 = stage[w][jj + 4 + half];
                int2 e3 = stage[w][jj + 6 + half];
                float4 v0 = *reinterpret_cast<const float4*>(h + (size_t)e0.x * DH + l4);
                float4 v1 = *reinterpret_cast<const float4*>(h + (size_t)e1.x * DH + l4);
                float4 v2 = *reinterpret_cast<const float4*>(h + (size_t)e2.x * DH + l4);
                float4 v3 = *reinterpret_cast<const float4*>(h + (size_t)e3.x * DH + l4);
                float w0 = __int_as_float(e0.y), w1 = __int_as_float(e1.y);
                float w2 = __int_as_float(e2.y), w3 = __int_as_float(e3.y);
                a0.x = fmaf(v0.x, w0, a0.x); a0.y = fmaf(v0.y, w0, a0.y);
                a0.z = fmaf(v0.z, w0, a0.z); a0.w = fmaf(v0.w, w0, a0.w);
                a1.x = fmaf(v1.x, w1, a1.x); a1.y = fmaf(v1.y, w1, a1.y);
                a1.z = fmaf(v1.z, w1, a1.z); a1.w = fmaf(v1.w, w1, a1.w);
                a2.x = fmaf(v2.x, w2, a2.x); a2.y = fmaf(v2.y, w2, a2.y);
                a2.z = fmaf(v2.z, w2, a2.z); a2.w = fmaf(v2.w, w2, a2.w);
                a3.x = fmaf(v3.x, w3, a3.x); a3.y = fmaf(v3.y, w3, a3.y);
                a3.z = fmaf(v3.z, w3, a3.z); a3.w = fmaf(v3.w, w3, a3.w);
            }
            __syncwarp();
        }

        float4 acc = make_float4(a0.x + a1.x + a2.x + a3.x,
                                 a0.y + a1.y + a2.y + a3.y,
                                 a0.z + a1.z + a2.z + a3.z,
                                 a0.w + a1.w + a2.w + a3.w);
        acc.x += __shfl_xor_sync(0xffffffffu, acc.x, 16);
        acc.y += __shfl_xor_sync(0xffffffffu, acc.y, 16);
        acc.z += __shfl_xor_sync(0xffffffffu, acc.z, 16);
        acc.w += __shfl_xor_sync(0xffffffffu, acc.w, 16);
        if (half == 0) {
            *reinterpret_cast<float4*>(agg + (size_t)r * DH + l4) = acc;
            ls0 += acc.x; lq0 = fmaf(acc.x, acc.x, lq0);
            ls1 += acc.y; lq1 = fmaf(acc.y, acc.y, lq1);
            ls2 += acc.z; lq2 = fmaf(acc.z, acc.z, lq2);
            ls3 += acc.w; lq3 = fmaf(acc.w, acc.w, lq3);
        }
    }

    __shared__ float ssum[8][64], ssq[8][64];
    if (half == 0) {
        ssum[w][l4 + 0] = ls0; ssum[w][l4 + 1] = ls1;
        ssum[w][l4 + 2] = ls2; ssum[w][l4 + 3] = ls3;
        ssq[w][l4 + 0] = lq0;  ssq[w][l4 + 1] = lq1;
        ssq[w][l4 + 2] = lq2;  ssq[w][l4 + 3] = lq3;
    }
    __syncthreads();
    if (tid < 64) {
        float S = 0.f, Q = 0.f;
        #pragma unroll
        for (int ww = 0; ww < 8; ww++) { S += ssum[ww][tid]; Q += ssq[ww][tid]; }
        atomicAdd(&gsum[tid], S);
        atomicAdd(&gsq[tid], Q);
    }
}

// ---------------- GEMM2: h2 = relu(bn1(agg1)) @ W2 (float2-col layout) -------
__global__ void gemm2_kernel(const float* __restrict__ W2,
                             const float* __restrict__ gamma1,
                             const float* __restrict__ beta1) {
    __shared__ float sW[DH * DH];   // 16 KB
    __shared__ float sx[32][DH];    // 8 KB
    __shared__ float s_scale[DH], s_shift[DH];
    int tid = threadIdx.x;
    if (tid < DH) {
        float mean = g_sum1[tid] * (1.0f / Nn);
        float var = g_sq1[tid] * (1.0f / Nn) - mean * mean;
        float sc = gamma1[tid] * rsqrtf(var + BN_EPS);
        s_scale[tid] = sc;
        s_shift[tid] = fmaf(-mean, sc, beta1[tid]);
    }
    for (int i = tid; i < DH * DH; i += 256) sW[i] = W2[i];
    __syncthreads();
    int warp = tid >> 5, lane = tid & 31;
    int c2 = lane * 2;

    for (int base = blockIdx.x * 32; base < Nn; base += gridDim.x * 32) {
        int r0 = base + warp * 4;
        #pragma unroll
        for (int r = 0; r < 4; r++) {
            int row = r0 + r;
            if (row < Nn) {
                float2 v = *reinterpret_cast<const float2*>(g_agg1 + (size_t)row * DH + c2);
                float2 o;
                o.x = fmaxf(fmaf(v.x, s_scale[c2], s_shift[c2]), 0.f);
                o.y = fmaxf(fmaf(v.y, s_scale[c2 + 1], s_shift[c2 + 1]), 0.f);
                *reinterpret_cast<float2*>(&sx[warp * 4 + r][c2]) = o;
            }
        }
        __syncwarp();

        float2 acc[4] = {};
        #pragma unroll 4
        for (int k4 = 0; k4 < DH / 4; k4++) {
            float4 xv[4];
            #pragma unroll
            for (int r = 0; r < 4; r++)
                xv[r] = *reinterpret_cast<const float4*>(&sx[warp * 4 + r][k4 * 4]);
            #pragma unroll
            for (int kk = 0; kk < 4; kk++) {
                int k = k4 * 4 + kk;
                float2 wv = *reinterpret_cast<const float2*>(&sW[k * DH + c2]);
                #pragma unroll
                for (int r = 0; r < 4; r++) {
                    float xs = (kk == 0) ? xv[r].x : (kk == 1) ? xv[r].y : (kk == 2) ? xv[r].z : xv[r].w;
                    acc[r].x = fmaf(xs, wv.x, acc[r].x);
                    acc[r].y = fmaf(xs, wv.y, acc[r].y);
                }
            }
        }

        #pragma unroll
        for (int r = 0; r < 4; r++) {
            int row = r0 + r;
            if (row < Nn)
                *reinterpret_cast<float2*>(g_h2 + (size_t)row * DH + c2) = acc[r];
        }
        __syncwarp();
    }
}

// ---------------- final: out = relu(bn2(agg2)) -------------------------------
__global__ void final_kernel(const float* __restrict__ gamma2,
                             const float* __restrict__ beta2,
                             float* __restrict__ out) {
    __shared__ float s_scale[DH], s_shift[DH];
    int tid = threadIdx.x;
    if (tid < DH) {
        float mean = g_sum2[tid] * (1.0f / Nn);
        float var = g_sq2[tid] * (1.0f / Nn) - mean * mean;
        float sc = gamma2[tid] * rsqrtf(var + BN_EPS);
        s_scale[tid] = sc;
        s_shift[tid] = fmaf(-mean, sc, beta2[tid]);
    }
    __syncthreads();
    int i = blockIdx.x * 256 + tid;
    if (i < Nn * DH) {
        int c = i & 63;
        out[i] = fmaxf(fmaf(g_agg2[i], s_scale[c], s_shift[c]), 0.f);
    }
}

// -----------------------------------------------------------------------------
extern "C" void kernel_launch(void* const* d_in, const int* in_sizes, int n_in,
                              void* d_out, int out_size) {
    const float* x      = (const float*)d_in[0];
    const void*  ei_sc  = d_in[1];
    const float* w_sc   = (const float*)d_in[2];
    // d_in[3] = edge_index_fc (unused by reference)
    const float* w_fc   = (const float*)d_in[4];
    const float* alpha  = (const float*)d_in[5];
    const float* W1     = (const float*)d_in[6];
    const float* b1     = (const float*)d_in[7];
    const float* W2     = (const float*)d_in[8];
    const float* b2     = (const float*)d_in[9];
    const float* gamma1 = (const float*)d_in[10];
    const float* beta1  = (const float*)d_in[11];
    const float* gamma2 = (const float*)d_in[12];
    const float* beta2  = (const float*)d_in[13];
    float* out = (float*)d_out;

    const int TB = 256;
    const int nblkE = (Ee + TB - 1) / TB;       // 6250

    // Fork gemm1 onto a NON-BLOCKING stream. R14 used cudaStreamPerThread,
    // which carries legacy-stream implicit sync -> the fork serialized in the
    // captured graph. cudaStreamNonBlocking is exempt from legacy sync.
    // Stream + events are host-side objects, created per call and intentionally
    // leaked (kernel_launch runs only a few times host-side; replays don't).
    cudaStream_t s2;
    cudaStreamCreateWithFlags(&s2, cudaStreamNonBlocking);
    cudaEvent_t ev_fork, ev_join;
    cudaEventCreateWithFlags(&ev_fork, cudaEventDisableTiming);
    cudaEventCreateWithFlags(&ev_join, cudaEventDisableTiming);

    cudaEventRecord(ev_fork, 0);                 // fork from capture stream
    cudaStreamWaitEvent(s2, ev_fork, 0);
    gemm1_kernel<<<592, TB, 0, s2>>>(x, W1);     // overlaps prologue below
    cudaEventRecord(ev_join, s2);

    init_kernel<<<196, TB>>>(alpha);
    mix_deg_kernel<<<nblkE, TB>>>(ei_sc, w_sc, w_fc);
    scan_a_kernel<<<196, TB>>>();
    scan_bc_kernel<<<196, TB>>>();
    fill_kernel<<<nblkE, TB>>>();

    cudaStreamWaitEvent(0, ev_join, 0);          // join: agg1 needs g_h1
    agg_kernel<1><<<592, TB>>>(b1);
    gemm2_kernel<<<592, TB>>>(W2, gamma1, beta1);
    agg_kernel<2><<<592, TB>>>(b2);
    final_kernel<<<(Nn * DH + TB - 1) / TB, TB>>>(gamma2, beta2, out);
}

// round 16
// speedup vs baseline: 1.2344x; 1.0038x over previous
#include <cuda_runtime.h>
#include <math.h>

#define Nn 50000
#define Ee 1600000
#define DIN 128
#define DH 64
#define BN_EPS 1e-5f

// ---------------- scratch (device globals; no allocation allowed) -------------
__device__ float  g_w[Ee];            // mixed weight (pre-norm)
__device__ int2   g_idx[Ee];          // (src, dst) as int32
__device__ int2   g_csr[Ee];          // dst-sorted: (src, bitcast(norm))
__device__ float2 g_degcnt[Nn];       // (weighted degree incl self, count) via red.v2
__device__ float  g_dinv[Nn];         // rsqrt(deg)
__device__ int    g_part[50176];      // block-local exclusive scan
__device__ int    g_bsum[196];
__device__ int    g_row_off[Nn + 1];  // CSR row offsets
__device__ int    g_cursor[Nn];       // fill cursors
__device__ float  g_h1[Nn * DH];      // x @ W1  (fp32: agg is issue-bound; fp16 was slower)
__device__ float  g_h2[Nn * DH];
__device__ float  g_agg1[Nn * DH];
__device__ float  g_agg2[Nn * DH];
__device__ float  g_sum1[DH], g_sq1[DH], g_sum2[DH], g_sq2[DH];
__device__ float  g_a;

// ---------------- init: deg=(1,0) self-loop, BN stats, sigmoid(alpha) --------
__global__ void init_kernel(const float* __restrict__ alpha) {
    int i = blockIdx.x * blockDim.x + threadIdx.x;
    if (i < Nn) g_degcnt[i] = make_float2(1.0f, 0.0f);
    if (i < DH) { g_sum1[i] = 0.f; g_sq1[i] = 0.f; g_sum2[i] = 0.f; g_sq2[i] = 0.f; }
    if (i == 0) g_a = 1.0f / (1.0f + expf(-alpha[0]));
}

// ---------------- mix weights, record (src,dst), fused degree+count red ------
__global__ void mix_deg_kernel(const void* __restrict__ ei,
                               const float* __restrict__ wsc,
                               const float* __restrict__ wfc) {
    int tid = threadIdx.x;
    int any = __syncthreads_or((int)((const unsigned*)ei)[2 * tid + 1]);
    int is64 = (any == 0);
    int e = blockIdx.x * blockDim.x + tid;
    if (e >= Ee) return;
    int s, d;
    if (is64) {
        const long long* p = (const long long*)ei;   // full-8B loads: full sectors
        s = (int)p[e];
        d = (int)p[(size_t)Ee + e];
    } else {
        const int* p = (const int*)ei;
        s = p[e];
        d = p[Ee + e];
    }
    float a = g_a;
    float w = a * wsc[e] + (1.0f - a) * wfc[e];
    g_w[e] = w;
    g_idx[e] = make_int2(s, d);
    float* dp = (float*)&g_degcnt[d];
    asm volatile("red.global.add.v2.f32 [%0], {%1,%2};"
                 :: "l"(dp), "f"(w), "f"(1.0f) : "memory");
}

// ---------------- scan part A (+ dinv fused) ---------------------------------
__global__ void scan_a_kernel() {
    __shared__ int s[256];
    int i = blockIdx.x * 256 + threadIdx.x;
    int v = 0;
    if (i < Nn) {
        float2 dc = g_degcnt[i];
        v = (int)dc.y;
        g_dinv[i] = (dc.x > 0.f) ? rsqrtf(fmaxf(dc.x, 1e-12f)) : 0.f;
    }
    s[threadIdx.x] = v;
    __syncthreads();
    #pragma unroll
    for (int off = 1; off < 256; off <<= 1) {
        int t = (threadIdx.x >= off) ? s[threadIdx.x - off] : 0;
        __syncthreads();
        s[threadIdx.x] += t;
        __syncthreads();
    }
    g_part[i] = s[threadIdx.x] - v;
    if (threadIdx.x == 255) g_bsum[blockIdx.x] = s[255];
}

// ---------------- GEMM1: h1 = x @ W1 (forked stream) -------------------------
// Half-warp owns 4 rows; thread owns 4 consecutive cols. Per k4: 4 broadcast
// LDG.128 (x) + 4 LDS.128 (W) for 128 FMAs -> 4x fewer L1tex ops per FMA than
// the staged version. No x staging: smem = 32 KB, no syncwarp in hot loop.
__global__ void gemm1_kernel(const float* __restrict__ x,
                             const float* __restrict__ W1) {
    __shared__ float sW[DIN * DH];      // 32 KB
    int tid = threadIdx.x;
    for (int i = tid; i < DIN * DH; i += 256) sW[i] = W1[i];
    __syncthreads();
    int warp = tid >> 5, lane = tid & 31, half = lane >> 4;
    int c4 = (lane & 15) * 4;

    for (int base = blockIdx.x * 64; base < Nn; base += gridDim.x * 64) {
        int r0 = base + warp * 8 + half * 4;
        if (r0 + 3 < Nn) {
            const float* xr = x + (size_t)r0 * DIN;
            float4 a0 = {}, a1 = {}, a2 = {}, a3 = {};
            #pragma unroll 4
            for (int k4 = 0; k4 < DIN / 4; k4++) {
                float4 x0 = *reinterpret_cast<const float4*>(xr + k4 * 4);
                float4 x1 = *reinterpret_cast<const float4*>(xr + DIN + k4 * 4);
                float4 x2 = *reinterpret_cast<const float4*>(xr + 2 * DIN + k4 * 4);
                float4 x3 = *reinterpret_cast<const float4*>(xr + 3 * DIN + k4 * 4);
                #pragma unroll
                for (int kk = 0; kk < 4; kk++) {
                    float4 wv = *reinterpret_cast<const float4*>(&sW[(k4 * 4 + kk) * DH + c4]);
                    float s0 = (kk == 0) ? x0.x : (kk == 1) ? x0.y : (kk == 2) ? x0.z : x0.w;
                    float s1 = (kk == 0) ? x1.x : (kk == 1) ? x1.y : (kk == 2) ? x1.z : x1.w;
                    float s2 = (kk == 0) ? x2.x : (kk == 1) ? x2.y : (kk == 2) ? x2.z : x2.w;
                    float s3 = (kk == 0) ? x3.x : (kk == 1) ? x3.y : (kk == 2) ? x3.z : x3.w;
                    a0.x = fmaf(s0, wv.x, a0.x); a0.y = fmaf(s0, wv.y, a0.y);
                    a0.z = fmaf(s0, wv.z, a0.z); a0.w = fmaf(s0, wv.w, a0.w);
                    a1.x = fmaf(s1, wv.x, a1.x); a1.y = fmaf(s1, wv.y, a1.y);
                    a1.z = fmaf(s1, wv.z, a1.z); a1.w = fmaf(s1, wv.w, a1.w);
                    a2.x = fmaf(s2, wv.x, a2.x); a2.y = fmaf(s2, wv.y, a2.y);
                    a2.z = fmaf(s2, wv.z, a2.z); a2.w = fmaf(s2, wv.w, a2.w);
                    a3.x = fmaf(s3, wv.x, a3.x); a3.y = fmaf(s3, wv.y, a3.y);
                    a3.z = fmaf(s3, wv.z, a3.z); a3.w = fmaf(s3, wv.w, a3.w);
                }
            }
            *reinterpret_cast<float4*>(g_h1 + (size_t)r0 * DH + c4) = a0;
            *reinterpret_cast<float4*>(g_h1 + ((size_t)r0 + 1) * DH + c4) = a1;
            *reinterpret_cast<float4*>(g_h1 + ((size_t)r0 + 2) * DH + c4) = a2;
            *reinterpret_cast<float4*>(g_h1 + ((size_t)r0 + 3) * DH + c4) = a3;
        } else {
            // tail: guard each row (rare)
            for (int r = 0; r < 4; r++) {
                int row = r0 + r;
                if (row >= Nn) break;
                const float* xr = x + (size_t)row * DIN;
                float4 a = {};
                for (int k4 = 0; k4 < DIN / 4; k4++) {
                    float4 xv = *reinterpret_cast<const float4*>(xr + k4 * 4);
                    #pragma unroll
                    for (int kk = 0; kk < 4; kk++) {
                        float4 wv = *reinterpret_cast<const float4*>(&sW[(k4 * 4 + kk) * DH + c4]);
                        float xs = (kk == 0) ? xv.x : (kk == 1) ? xv.y : (kk == 2) ? xv.z : xv.w;
                        a.x = fmaf(xs, wv.x, a.x); a.y = fmaf(xs, wv.y, a.y);
                        a.z = fmaf(xs, wv.z, a.z); a.w = fmaf(xs, wv.w, a.w);
                    }
                }
                *reinterpret_cast<float4*>(g_h1 + (size_t)row * DH + c4) = a;
            }
        }
    }
}

// ---------------- scan B+C merged: each block redundantly scans g_bsum -------
__global__ void scan_bc_kernel() {
    __shared__ int s[256];
    __shared__ int s_off;
    int tid = threadIdx.x;
    int v = (tid < 196) ? g_bsum[tid] : 0;
    s[tid] = v;
    __syncthreads();
    #pragma unroll
    for (int off = 1; off < 256; off <<= 1) {
        int t = (tid >= off) ? s[tid - off] : 0;
        __syncthreads();
        s[tid] += t;
        __syncthreads();
    }
    if (tid == blockIdx.x) s_off = s[tid] - v;   // exclusive prefix of this block
    __syncthreads();
    int i = blockIdx.x * 256 + tid;
    if (i < Nn) {
        int o = g_part[i] + s_off;
        g_row_off[i] = o;
        g_cursor[i] = o;
    }
    if (i == 0) g_row_off[Nn] = Ee;
}

// ---------------- CSR fill: norm computed here -------------------------------
__global__ void fill_kernel() {
    int e = blockIdx.x * blockDim.x + threadIdx.x;
    if (e >= Ee) return;
    int2 sd = g_idx[e];
    float nrm = g_w[e] * g_dinv[sd.x] * g_dinv[sd.y];
    int pos = atomicAdd(&g_cursor[sd.y], 1);
    g_csr[pos] = make_int2(sd.x, __float_as_int(nrm));
}

// ---------------- CSR aggregation (fp32 gather) + fused BN stats -------------
template <int L>
__global__ void agg_kernel(const float* __restrict__ bias) {
    const float* __restrict__ h = (L == 1) ? g_h1 : g_h2;
    float* agg  = (L == 1) ? g_agg1 : g_agg2;
    float* gsum = (L == 1) ? g_sum1 : g_sum2;
    float* gsq  = (L == 1) ? g_sq1  : g_sq2;

    __shared__ int2 stage[8][32];

    int tid = threadIdx.x;
    int w = tid >> 5, lane = tid & 31, half = lane >> 4;
    int l4 = (lane & 15) * 4;
    int wg = (blockIdx.x << 3) + w;
    int nw = gridDim.x << 3;
    float4 bb = *reinterpret_cast<const float4*>(bias + l4);
    float ls0 = 0, ls1 = 0, ls2 = 0, ls3 = 0;
    float lq0 = 0, lq1 = 0, lq2 = 0, lq3 = 0;

    for (int r = wg; r < Nn; r += nw) {
        int beg = g_row_off[r], end = g_row_off[r + 1];
        float4 a0, a1, a2, a3;
        a1 = a2 = a3 = make_float4(0.f, 0.f, 0.f, 0.f);
        if (half == 0) {
            float di = g_dinv[r];
            float sn = di * di;  // self-loop: dinv*1*dinv
            float4 hv = *reinterpret_cast<const float4*>(h + (size_t)r * DH + l4);
            a0 = make_float4(fmaf(hv.x, sn, bb.x), fmaf(hv.y, sn, bb.y),
                             fmaf(hv.z, sn, bb.z), fmaf(hv.w, sn, bb.w));
        } else {
            a0 = make_float4(0.f, 0.f, 0.f, 0.f);
        }

        for (int base = beg; base < end; base += 32) {
            int m = end - base;
            if (m > 32) m = 32;
            stage[w][lane] = (lane < m) ? g_csr[base + lane] : make_int2(0, 0);
            __syncwarp();

            int jj = 0;
            for (; jj + 8 <= m; jj += 8) {
                int2 e0 = stage[w][jj + half];
                int2 e1 = stage[w][jj + 2 + half];
                int2 e2 = stage[w][jj + 4 + half];
                int2 e3 = stage[w][jj + 6 + half];
                float4 v0 = *reinterpret_cast<const float4*>(h + (size_t)e0.x * DH + l4);
                float4 v1 = *reinterpret_cast<const float4*>(h + (size_t)e1.x * DH + l4);
                float4 v2 = *reinterpret_cast<const float4*>(h + (size_t)e2.x * DH + l4);
                float4 v3 = *reinterpret_cast<const float4*>(h + (size_t)e3.x * DH + l4);
                float w0 = __int_as_float(e0.y), w1 = __int_as_float(e1.y);
                float w2 = __int_as_float(e2.y), w3 = __int_as_float(e3.y);
                a0.x = fmaf(v0.x, w0, a0.x); a0.y = fmaf(v0.y, w0, a0.y);
                a0.z = fmaf(v0.z, w0, a0.z); a0.w = fmaf(v0.w, w0, a0.w);
                a1.x = fmaf(v1.x, w1, a1.x); a1.y = fmaf(v1.y, w1, a1.y);
                a1.z = fmaf(v1.z, w1, a1.z); a1.w = fmaf(v1.w, w1, a1.w);
                a2.x = fmaf(v2.x, w2, a2.x); a2.y = fmaf(v2.y, w2, a2.y);
                a2.z = fmaf(v2.z, w2, a2.z); a2.w = fmaf(v2.w, w2, a2.w);
                a3.x = fmaf(v3.x, w3, a3.x); a3.y = fmaf(v3.y, w3, a3.y);
                a3.z = fmaf(v3.z, w3, a3.z); a3.w = fmaf(v3.w, w3, a3.w);
            }
            if (jj < m) {
                int2 e0 = stage[w][jj + half];
                int2 e1 = stage[w][jj + 2 + half];
                int2 e2 = stage[w][jj + 4 + half];
                int2 e3 = stage[w][jj + 6 + half];
                float4 v0 = *reinterpret_cast<const float4*>(h + (size_t)e0.x * DH + l4);
                float4 v1 = *reinterpret_cast<const float4*>(h + (size_t)e1.x * DH + l4);
                float4 v2 = *reinterpret_cast<const float4*>(h + (size_t)e2.x * DH + l4);
                float4 v3 = *reinterpret_cast<const float4*>(h + (size_t)e3.x * DH + l4);
                float w0 = __int_as_float(e0.y), w1 = __int_as_float(e1.y);
                float w2 = __int_as_float(e2.y), w3 = __int_as_float(e3.y);
                a0.x = fmaf(v0.x, w0, a0.x); a0.y = fmaf(v0.y, w0, a0.y);
                a0.z = fmaf(v0.z, w0, a0.z); a0.w = fmaf(v0.w, w0, a0.w);
                a1.x = fmaf(v1.x, w1, a1.x); a1.y = fmaf(v1.y, w1, a1.y);
                a1.z = fmaf(v1.z, w1, a1.z); a1.w = fmaf(v1.w, w1, a1.w);
                a2.x = fmaf(v2.x, w2, a2.x); a2.y = fmaf(v2.y, w2, a2.y);
                a2.z = fmaf(v2.z, w2, a2.z); a2.w = fmaf(v2.w, w2, a2.w);
                a3.x = fmaf(v3.x, w3, a3.x); a3.y = fmaf(v3.y, w3, a3.y);
                a3.z = fmaf(v3.z, w3, a3.z); a3.w = fmaf(v3.w, w3, a3.w);
            }
            __syncwarp();
        }

        float4 acc = make_float4(a0.x + a1.x + a2.x + a3.x,
                                 a0.y + a1.y + a2.y + a3.y,
                                 a0.z + a1.z + a2.z + a3.z,
                                 a0.w + a1.w + a2.w + a3.w);
        acc.x += __shfl_xor_sync(0xffffffffu, acc.x, 16);
        acc.y += __shfl_xor_sync(0xffffffffu, acc.y, 16);
        acc.z += __shfl_xor_sync(0xffffffffu, acc.z, 16);
        acc.w += __shfl_xor_sync(0xffffffffu, acc.w, 16);
        if (half == 0) {
            *reinterpret_cast<float4*>(agg + (size_t)r * DH + l4) = acc;
            ls0 += acc.x; lq0 = fmaf(acc.x, acc.x, lq0);
            ls1 += acc.y; lq1 = fmaf(acc.y, acc.y, lq1);
            ls2 += acc.z; lq2 = fmaf(acc.z, acc.z, lq2);
            ls3 += acc.w; lq3 = fmaf(acc.w, acc.w, lq3);
        }
    }

    __shared__ float ssum[8][64], ssq[8][64];
    if (half == 0) {
        ssum[w][l4 + 0] = ls0; ssum[w][l4 + 1] = ls1;
        ssum[w][l4 + 2] = ls2; ssum[w][l4 + 3] = ls3;
        ssq[w][l4 + 0] = lq0;  ssq[w][l4 + 1] = lq1;
        ssq[w][l4 + 2] = lq2;  ssq[w][l4 + 3] = lq3;
    }
    __syncthreads();
    if (tid < 64) {
        float S = 0.f, Q = 0.f;
        #pragma unroll
        for (int ww = 0; ww < 8; ww++) { S += ssum[ww][tid]; Q += ssq[ww][tid]; }
        atomicAdd(&gsum[tid], S);
        atomicAdd(&gsq[tid], Q);
    }
}

// ---------------- GEMM2: h2 = relu(bn1(agg1)) @ W2 (same restructure) --------
// BN+ReLU applied on the fly to the streamed agg1 rows (once per element).
__global__ void gemm2_kernel(const float* __restrict__ W2,
                             const float* __restrict__ gamma1,
                             const float* __restrict__ beta1) {
    __shared__ float sW[DH * DH];   // 16 KB
    __shared__ float s_scale[DH], s_shift[DH];
    int tid = threadIdx.x;
    if (tid < DH) {
        float mean = g_sum1[tid] * (1.0f / Nn);
        float var = g_sq1[tid] * (1.0f / Nn) - mean * mean;
        float sc = gamma1[tid] * rsqrtf(var + BN_EPS);
        s_scale[tid] = sc;
        s_shift[tid] = fmaf(-mean, sc, beta1[tid]);
    }
    for (int i = tid; i < DH * DH; i += 256) sW[i] = W2[i];
    __syncthreads();
    int warp = tid >> 5, lane = tid & 31, half = lane >> 4;
    int c4 = (lane & 15) * 4;

    for (int base = blockIdx.x * 64; base < Nn; base += gridDim.x * 64) {
        int r0 = base + warp * 8 + half * 4;
        if (r0 >= Nn) continue;
        int nrows = Nn - r0;
        if (nrows > 4) nrows = 4;
        const float* xr = g_agg1 + (size_t)r0 * DH;
        float4 a0 = {}, a1 = {}, a2 = {}, a3 = {};
        #pragma unroll 4
        for (int k4 = 0; k4 < DH / 4; k4++) {
            float4 sc4 = *reinterpret_cast<const float4*>(&s_scale[k4 * 4]);
            float4 sh4 = *reinterpret_cast<const float4*>(&s_shift[k4 * 4]);
            float4 x0, x1, x2, x3;
            x1 = x2 = x3 = make_float4(0.f, 0.f, 0.f, 0.f);
            x0 = *reinterpret_cast<const float4*>(xr + k4 * 4);
            if (nrows > 1) x1 = *reinterpret_cast<const float4*>(xr + DH + k4 * 4);
            if (nrows > 2) x2 = *reinterpret_cast<const float4*>(xr + 2 * DH + k4 * 4);
            if (nrows > 3) x3 = *reinterpret_cast<const float4*>(xr + 3 * DH + k4 * 4);
            // BN + ReLU (per element, once)
            x0.x = fmaxf(fmaf(x0.x, sc4.x, sh4.x), 0.f); x0.y = fmaxf(fmaf(x0.y, sc4.y, sh4.y), 0.f);
            x0.z = fmaxf(fmaf(x0.z, sc4.z, sh4.z), 0.f); x0.w = fmaxf(fmaf(x0.w, sc4.w, sh4.w), 0.f);
            x1.x = fmaxf(fmaf(x1.x, sc4.x, sh4.x), 0.f); x1.y = fmaxf(fmaf(x1.y, sc4.y, sh4.y), 0.f);
            x1.z = fmaxf(fmaf(x1.z, sc4.z, sh4.z), 0.f); x1.w = fmaxf(fmaf(x1.w, sc4.w, sh4.w), 0.f);
            x2.x = fmaxf(fmaf(x2.x, sc4.x, sh4.x), 0.f); x2.y = fmaxf(fmaf(x2.y, sc4.y, sh4.y), 0.f);
            x2.z = fmaxf(fmaf(x2.z, sc4.z, sh4.z), 0.f); x2.w = fmaxf(fmaf(x2.w, sc4.w, sh4.w), 0.f);
            x3.x = fmaxf(fmaf(x3.x, sc4.x, sh4.x), 0.f); x3.y = fmaxf(fmaf(x3.y, sc4.y, sh4.y), 0.f);
            x3.z = fmaxf(fmaf(x3.z, sc4.z, sh4.z), 0.f); x3.w = fmaxf(fmaf(x3.w, sc4.w, sh4.w), 0.f);
            // NOTE: BN(0)!=0 in general, but rows 1-3 are only used when valid;
            // invalid-row x values feed accumulators that are never stored.
            #pragma unroll
            for (int kk = 0; kk < 4; kk++) {
                float4 wv = *reinterpret_cast<const float4*>(&sW[(k4 * 4 + kk) * DH + c4]);
                float s0 = (kk == 0) ? x0.x : (kk == 1) ? x0.y : (kk == 2) ? x0.z : x0.w;
                float s1 = (kk == 0) ? x1.x : (kk == 1) ? x1.y : (kk == 2) ? x1.z : x1.w;
                float s2 = (kk == 0) ? x2.x : (kk == 1) ? x2.y : (kk == 2) ? x2.z : x2.w;
                float s3 = (kk == 0) ? x3.x : (kk == 1) ? x3.y : (kk == 2) ? x3.z : x3.w;
                a0.x = fmaf(s0, wv.x, a0.x); a0.y = fmaf(s0, wv.y, a0.y);
                a0.z = fmaf(s0, wv.z, a0.z); a0.w = fmaf(s0, wv.w, a0.w);
                a1.x = fmaf(s1, wv.x, a1.x); a1.y = fmaf(s1, wv.y, a1.y);
                a1.z = fmaf(s1, wv.z, a1.z); a1.w = fmaf(s1, wv.w, a1.w);
                a2.x = fmaf(s2, wv.x, a2.x); a2.y = fmaf(s2, wv.y, a2.y);
                a2.z = fmaf(s2, wv.z, a2.z); a2.w = fmaf(s2, wv.w, a2.w);
                a3.x = fmaf(s3, wv.x, a3.x); a3.y = fmaf(s3, wv.y, a3.y);
                a3.z = fmaf(s3, wv.z, a3.z); a3.w = fmaf(s3, wv.w, a3.w);
            }
        }
        *reinterpret_cast<float4*>(g_h2 + (size_t)r0 * DH + c4) = a0;
        if (nrows > 1) *reinterpret_cast<float4*>(g_h2 + ((size_t)r0 + 1) * DH + c4) = a1;
        if (nrows > 2) *reinterpret_cast<float4*>(g_h2 + ((size_t)r0 + 2) * DH + c4) = a2;
        if (nrows > 3) *reinterpret_cast<float4*>(g_h2 + ((size_t)r0 + 3) * DH + c4) = a3;
    }
}

// ---------------- final: out = relu(bn2(agg2)) -------------------------------
__global__ void final_kernel(const float* __restrict__ gamma2,
                             const float* __restrict__ beta2,
                             float* __restrict__ out) {
    __shared__ float s_scale[DH], s_shift[DH];
    int tid = threadIdx.x;
    if (tid < DH) {
        float mean = g_sum2[tid] * (1.0f / Nn);
        float var = g_sq2[tid] * (1.0f / Nn) - mean * mean;
        float sc = gamma2[tid] * rsqrtf(var + BN_EPS);
        s_scale[tid] = sc;
        s_shift[tid] = fmaf(-mean, sc, beta2[tid]);
    }
    __syncthreads();
    int i = blockIdx.x * 256 + tid;
    if (i < Nn * DH) {
        int c = i & 63;
        out[i] = fmaxf(fmaf(g_agg2[i], s_scale[c], s_shift[c]), 0.f);
    }
}

// -----------------------------------------------------------------------------
extern "C" void kernel_launch(void* const* d_in, const int* in_sizes, int n_in,
                              void* d_out, int out_size) {
    const float* x      = (const float*)d_in[0];
    const void*  ei_sc  = d_in[1];
    const float* w_sc   = (const float*)d_in[2];
    // d_in[3] = edge_index_fc (unused by reference)
    const float* w_fc   = (const float*)d_in[4];
    const float* alpha  = (const float*)d_in[5];
    const float* W1     = (const float*)d_in[6];
    const float* b1     = (const float*)d_in[7];
    const float* W2     = (const float*)d_in[8];
    const float* b2     = (const float*)d_in[9];
    const float* gamma1 = (const float*)d_in[10];
    const float* beta1  = (const float*)d_in[11];
    const float* gamma2 = (const float*)d_in[12];
    const float* beta2  = (const float*)d_in[13];
    float* out = (float*)d_out;

    const int TB = 256;
    const int nblkE = (Ee + TB - 1) / TB;       // 6250

    // Fork gemm1 onto a non-blocking stream (graph-captured fork/join).
    // Stream + events are host objects, created per call and intentionally
    // leaked (host code runs only a few times; graph replays don't).
    cudaStream_t s2;
    cudaStreamCreateWithFlags(&s2, cudaStreamNonBlocking);
    cudaEvent_t ev_fork, ev_join;
    cudaEventCreateWithFlags(&ev_fork, cudaEventDisableTiming);
    cudaEventCreateWithFlags(&ev_join, cudaEventDisableTiming);

    cudaEventRecord(ev_fork, 0);                 // fork from capture stream
    cudaStreamWaitEvent(s2, ev_fork, 0);
    gemm1_kernel<<<592, TB, 0, s2>>>(x, W1);     // overlaps prologue below
    cudaEventRecord(ev_join, s2);

    init_kernel<<<196, TB>>>(alpha);
    mix_deg_kernel<<<nblkE, TB>>>(ei_sc, w_sc, w_fc);
    scan_a_kernel<<<196, TB>>>();
    scan_bc_kernel<<<196, TB>>>();
    fill_kernel<<<nblkE, TB>>>();

    cudaStreamWaitEvent(0, ev_join, 0);          // join: agg1 needs g_h1
    agg_kernel<1><<<592, TB>>>(b1);
    gemm2_kernel<<<592, TB>>>(W2, gamma1, beta1);
    agg_kernel<2><<<592, TB>>>(b2);
    final_kernel<<<(Nn * DH + TB - 1) / TB, TB>>>(gamma2, beta2, out);
}